// round 1
// baseline (speedup 1.0000x reference)
#include <cuda_runtime.h>

// Problem constants
#define BQ   4
#define NA   64
#define EF   128
#define NX   48
#define GSZ  (48*48*48)          // 110592
#define TP   16                  // grid points per tile
#define THREADS 256
#define NBLK 148
#define TILES_PER_B (GSZ / TP)   // 6912
#define NTILES (BQ * TILES_PER_B) // 27648
#define XPAD 20                  // padded row stride for xsT (float4-aligned)

// Shared memory layout (floats):
// Fs   : 4*64*128 = 32768
// W1s  : 128*128  = 16384
// b1s  : 128
// W2s  : 128
// poss : 4*64*3   = 768
// org  : 12
// stp  : 12
// wT   : 64*16    = 1024
// xsT  : 128*20   = 2560
// red  : 16
// bns  : 4 (ints)
#define SM_FLOATS (32768 + 16384 + 128 + 128 + 768 + 12 + 12 + 1024 + 2560 + 16 + 4)
#define SMEM_BYTES (SM_FLOATS * 4)

__global__ void __launch_bounds__(THREADS, 1)
dgnn_kernel(const float* __restrict__ pos,
            const float* __restrict__ feat,
            const float* __restrict__ origin,
            const float* __restrict__ lattice,
            const float* __restrict__ scale_p,
            const float* __restrict__ W1,
            const float* __restrict__ b1,
            const float* __restrict__ W2,
            const float* __restrict__ b2_p,
            const int*   __restrict__ bnodes,
            float* __restrict__ out,
            float* __restrict__ cout)
{
    extern __shared__ float sm[];
    float* Fs   = sm;                 // [b][n][e]
    float* W1s  = Fs + 32768;         // [e][j]
    float* b1s  = W1s + 16384;
    float* W2s  = b1s + 128;
    float* poss = W2s + 128;          // [b][n][3]
    float* org  = poss + 768;         // [b][3]
    float* stp  = org + 12;           // [b][3] = diag/47
    float* wT   = stp + 12;           // [n][t]  64 x 16
    float* xsT  = wT + 1024;          // [e][t]  128 x XPAD
    float* red  = xsT + 2560;         // [16]
    int*   bns  = (int*)(red + 16);   // [4]

    const int tid = threadIdx.x;

    // ---- one-time preload into shared ----
    for (int i = tid; i < 8192; i += THREADS)
        ((float4*)Fs)[i] = ((const float4*)feat)[i];
    for (int i = tid; i < 4096; i += THREADS)
        ((float4*)W1s)[i] = ((const float4*)W1)[i];
    if (tid < 128) { b1s[tid] = b1[tid]; W2s[tid] = W2[tid]; }
    for (int i = tid; i < 768; i += THREADS) poss[i] = pos[i];
    if (tid < 12) {
        org[tid] = origin[tid];
        int b = tid / 3, d = tid % 3;
        stp[tid] = lattice[b * 9 + d * 4] * (1.0f / 47.0f);
    }
    if (tid < 4)  bns[tid] = bnodes[tid];
    if (tid < 16) red[tid] = 0.0f;

    const float s   = scale_p[0];
    const float s2  = s * s;
    const float b2v = b2_p[0];
    __syncthreads();

    const int e   = tid & 127;   // column index (E and hidden J)
    const int grp = tid >> 7;    // 0 or 1
    const int tb  = grp * 8;     // this group's t offset

    for (int tile = blockIdx.x; tile < NTILES; tile += gridDim.x) {
        const int b  = tile / TILES_PER_B;
        const int g0 = (tile - b * TILES_PER_B) * TP;

        // ---- phase 1: Lorentzian weights, transposed wT[n][t] ----
        {
            const int t  = tid & 15;
            const int n0 = tid >> 4;     // 0..15
            const int g  = g0 + t;
            const int iz = g % NX;
            const int r  = g / NX;
            const int iy = r % NX;
            const int ix = r / NX;
            const float gx = org[b * 3 + 0] + (float)ix * stp[b * 3 + 0];
            const float gy = org[b * 3 + 1] + (float)iy * stp[b * 3 + 1];
            const float gz = org[b * 3 + 2] + (float)iz * stp[b * 3 + 2];
            const int bn = bns[b];
            #pragma unroll
            for (int p = 0; p < 4; p++) {
                const int n = n0 + p * 16;
                const float dx = gx - poss[(b * 64 + n) * 3 + 0];
                const float dy = gy - poss[(b * 64 + n) * 3 + 1];
                const float dz = gz - poss[(b * 64 + n) * 3 + 2];
                const float d2 = dx * dx + dy * dy + dz * dz;
                const float w  = (n < bn) ? __fdividef(s, s2 + d2) : 0.0f;
                wT[n * 16 + t] = w;
            }
        }
        __syncthreads();

        // ---- phase 2: x[t][e] = sum_n wT[n][t] * F[b][n][e] ----
        float x[8];
        #pragma unroll
        for (int k = 0; k < 8; k++) x[k] = 0.0f;
        {
            const float* Fb = Fs + (b * 64) * 128 + e;
            #pragma unroll 8
            for (int n = 0; n < 64; n++) {
                const float f = Fb[n * 128];
                const float4 wa = *(const float4*)&wT[n * 16 + tb];
                const float4 wb = *(const float4*)&wT[n * 16 + tb + 4];
                x[0] += wa.x * f; x[1] += wa.y * f;
                x[2] += wa.z * f; x[3] += wa.w * f;
                x[4] += wb.x * f; x[5] += wb.y * f;
                x[6] += wb.z * f; x[7] += wb.w * f;
            }
        }
        // write c to gmem + transposed xsT to shared
        {
            const long pbase = ((long)b * GSZ + g0 + tb) * 128 + e;
            #pragma unroll
            for (int k = 0; k < 8; k++) {
                cout[pbase + (long)k * 128] = x[k];
                xsT[e * XPAD + tb + k] = x[k];
            }
        }
        __syncthreads();

        // ---- phase 3: h[t][j] = relu(b1[j] + sum_e x[t][e]*W1[e][j]) ----
        float h[8];
        #pragma unroll
        for (int k = 0; k < 8; k++) h[k] = b1s[e];
        #pragma unroll 4
        for (int ee = 0; ee < 128; ee++) {
            const float w1 = W1s[ee * 128 + e];
            const float4 xa = *(const float4*)&xsT[ee * XPAD + tb];
            const float4 xb = *(const float4*)&xsT[ee * XPAD + tb + 4];
            h[0] += xa.x * w1; h[1] += xa.y * w1;
            h[2] += xa.z * w1; h[3] += xa.w * w1;
            h[4] += xb.x * w1; h[5] += xb.y * w1;
            h[6] += xb.z * w1; h[7] += xb.w * w1;
        }
        // out partials: relu(h) * W2[j], reduce over j within group
        {
            const float w2 = W2s[e];
            #pragma unroll
            for (int k = 0; k < 8; k++) {
                float v = fmaxf(h[k], 0.0f) * w2;
                v += __shfl_xor_sync(0xffffffff, v, 16);
                v += __shfl_xor_sync(0xffffffff, v, 8);
                v += __shfl_xor_sync(0xffffffff, v, 4);
                v += __shfl_xor_sync(0xffffffff, v, 2);
                v += __shfl_xor_sync(0xffffffff, v, 1);
                if ((tid & 31) == 0) atomicAdd(&red[tb + k], v);
            }
        }
        __syncthreads();
        if (tid < 16) {
            out[(long)b * GSZ + g0 + tid] = red[tid] + b2v;
            red[tid] = 0.0f;   // same thread re-zeros before anyone can atomicAdd again
        }
        // no extra barrier needed: next-tile wT writes are ordered after the
        // __syncthreads above, and red atomics only occur after two more barriers.
    }
}

extern "C" void kernel_launch(void* const* d_in, const int* in_sizes, int n_in,
                              void* d_out, int out_size)
{
    const float* pos     = (const float*)d_in[0];
    const float* feat    = (const float*)d_in[1];
    const float* origin  = (const float*)d_in[2];
    const float* lattice = (const float*)d_in[3];
    const float* scale   = (const float*)d_in[4];
    const float* W1      = (const float*)d_in[5];
    const float* b1      = (const float*)d_in[6];
    const float* W2      = (const float*)d_in[7];
    const float* b2      = (const float*)d_in[8];
    const int*   bn      = (const int*)  d_in[9];

    float* out  = (float*)d_out;                       // [B, 48,48,48]
    float* cout = out + (long)BQ * GSZ;                // [B, 48,48,48, 128]

    cudaFuncSetAttribute(dgnn_kernel,
                         cudaFuncAttributeMaxDynamicSharedMemorySize, SMEM_BYTES);

    dgnn_kernel<<<NBLK, THREADS, SMEM_BYTES>>>(
        pos, feat, origin, lattice, scale, W1, b1, b2 ? W2 : W2, b2, bn, out, cout);
}

// round 2
// speedup vs baseline: 2.1087x; 2.1087x over previous
#include <cuda_runtime.h>

#define NX      48
#define GSZ     (48*48*48)        // 110592
#define TP      128               // grid points per tile
#define THREADS 256
#define NBLK    148
#define TILES_PER_B (GSZ/TP)      // 864
#define BLKS_PER_B  (NBLK/4)      // 37

typedef unsigned long long u64;

// Shared layout (floats), all 16B aligned:
// Fs   [64][128]      8192   (one batch's features)
// W1s  [128][128]     16384
// wT   [64][128]      8192   (weights, [n][t])
// xsT  [128][128]     16384  (x transposed, 16B-chunk XOR swizzle along t)
// b1s 128, W2s 128, poss 192, orgb 4, stpb 4
#define SM_FLOATS (8192 + 16384 + 8192 + 16384 + 128 + 128 + 192 + 8)
#define SMEM_BYTES (SM_FLOATS * 4)

__device__ __forceinline__ u64 dup2(float f) {
    u64 r; asm("mov.b64 %0, {%1, %1};" : "=l"(r) : "f"(f)); return r;
}
__device__ __forceinline__ void fma2(u64 &d, u64 a, u64 b) {
    asm("fma.rn.f32x2 %0, %1, %2, %0;" : "+l"(d) : "l"(a), "l"(b));
}
__device__ __forceinline__ float2 unpk(u64 v) {
    float2 r; asm("mov.b64 {%0, %1}, %2;" : "=f"(r.x), "=f"(r.y) : "l"(v)); return r;
}

__global__ void __launch_bounds__(THREADS, 1)
dgnn2_kernel(const float* __restrict__ pos,
             const float* __restrict__ feat,
             const float* __restrict__ origin,
             const float* __restrict__ lattice,
             const float* __restrict__ scale_p,
             const float* __restrict__ W1,
             const float* __restrict__ b1,
             const float* __restrict__ W2,
             const float* __restrict__ b2_p,
             const int*   __restrict__ bnodes,
             float* __restrict__ out,
             float* __restrict__ cout)
{
    extern __shared__ float sm[];
    float* Fs   = sm;                  // [n][e]
    float* W1s  = Fs   + 8192;         // [ee][j]
    float* wT   = W1s  + 16384;        // [n][t]
    float* xsT  = wT   + 8192;         // [e][t] (swizzled)
    float* b1s  = xsT  + 16384;
    float* W2s  = b1s  + 128;
    float* poss = W2s  + 128;          // [n][3]
    float* orgb = poss + 192;          // [3]
    float* stpb = orgb + 4;            // [3]

    const int tid = threadIdx.x;
    const int b   = blockIdx.x & 3;    // batch for this block
    const int qb  = blockIdx.x >> 2;   // block index within batch (0..36)

    // ---- one-time preload ----
    for (int i = tid; i < 2048; i += THREADS)
        ((float4*)Fs)[i] = ((const float4*)(feat + b * 8192))[i];
    for (int i = tid; i < 4096; i += THREADS)
        ((float4*)W1s)[i] = ((const float4*)W1)[i];
    if (tid < 128) { b1s[tid] = b1[tid]; W2s[tid] = W2[tid]; }
    if (tid < 192) poss[tid] = pos[b * 192 + tid];
    if (tid < 3) {
        orgb[tid] = origin[b * 3 + tid];
        stpb[tid] = lattice[b * 9 + tid * 4] * (1.0f / 47.0f);
    }
    const float s   = scale_p[0];
    const float s2  = s * s;
    const float b2v = b2_p[0];
    const int   bn  = bnodes[b];
    __syncthreads();

    const int lane = tid & 31;
    const int e4   = (tid & 31) * 4;   // column base (E in phase2, J in phase3)
    const int tg   = tid >> 5;         // 0..7
    const int t0   = tg * 16;          // 16 grid points per thread
    const int swz2 = lane & 7;         // (e>>2)&7 for all 4 rows of this thread

    for (int tile = qb; tile < TILES_PER_B; tile += BLKS_PER_B) {
        const int g0 = tile * TP;

        // ================= phase 1: Lorentzian weights wT[n][t] =============
        {
            const int t  = tid & 127;          // this thread's grid point
            const int ng = (tid >> 7) * 32;    // its 32-atom slab
            const int g  = g0 + t;
            const int ix = g / 2304;
            const int rm = g - ix * 2304;
            const int iy = rm / 48;
            const int iz = rm - iy * 48;
            const float gx = orgb[0] + (float)ix * stpb[0];
            const float gy = orgb[1] + (float)iy * stpb[1];
            const float gz = orgb[2] + (float)iz * stpb[2];
            #pragma unroll 8
            for (int k = 0; k < 32; k++) {
                const int n = ng + k;
                const float dx = gx - poss[n * 3 + 0];
                const float dy = gy - poss[n * 3 + 1];
                const float dz = gz - poss[n * 3 + 2];
                const float d2 = dx * dx + dy * dy + dz * dz;
                wT[n * 128 + t] = (n < bn) ? __fdividef(s, s2 + d2) : 0.0f;
            }
        }
        __syncthreads();

        // ================= phase 2: x[t][e] = sum_n w[n][t] * F[n][e] ========
        u64 acc[4][8];
        #pragma unroll
        for (int r = 0; r < 4; r++)
            #pragma unroll
            for (int p = 0; p < 8; p++) acc[r][p] = 0ull;

        #pragma unroll 4
        for (int n = 0; n < 64; n++) {
            const float4 f = *(const float4*)&Fs[n * 128 + e4];
            u64 df[4];
            df[0] = dup2(f.x); df[1] = dup2(f.y);
            df[2] = dup2(f.z); df[3] = dup2(f.w);
            const ulonglong2* wp = (const ulonglong2*)&wT[n * 128 + t0];
            const ulonglong2 wa = wp[0], wb = wp[1], wc = wp[2], wd = wp[3];
            const u64 w[8] = {wa.x, wa.y, wb.x, wb.y, wc.x, wc.y, wd.x, wd.y};
            #pragma unroll
            for (int r = 0; r < 4; r++)
                #pragma unroll
                for (int p = 0; p < 8; p++) fma2(acc[r][p], df[r], w[p]);
        }

        // write xsT (swizzled 16B chunks) + cout (coalesced float4 over e)
        #pragma unroll
        for (int r = 0; r < 4; r++) {
            #pragma unroll
            for (int jj = 0; jj < 4; jj++) {
                const int c = (tg * 4 + jj) ^ swz2;
                ulonglong2 v; v.x = acc[r][2 * jj]; v.y = acc[r][2 * jj + 1];
                *(ulonglong2*)&xsT[(e4 + r) * 128 + c * 4] = v;
            }
        }
        {
            const size_t base = ((size_t)b * GSZ + g0) * 128 + e4;
            #pragma unroll
            for (int p = 0; p < 8; p++) {
                const float2 a0 = unpk(acc[0][p]);
                const float2 a1 = unpk(acc[1][p]);
                const float2 a2 = unpk(acc[2][p]);
                const float2 a3 = unpk(acc[3][p]);
                float4 v0 = make_float4(a0.x, a1.x, a2.x, a3.x);
                float4 v1 = make_float4(a0.y, a1.y, a2.y, a3.y);
                *(float4*)&cout[base + (size_t)(t0 + 2 * p) * 128]     = v0;
                *(float4*)&cout[base + (size_t)(t0 + 2 * p + 1) * 128] = v1;
            }
        }
        __syncthreads();

        // ================= phase 3: h[t][j] = relu(b1 + sum_e x*W1) ==========
        #pragma unroll
        for (int r = 0; r < 4; r++) {
            const u64 bb = dup2(b1s[e4 + r]);
            #pragma unroll
            for (int p = 0; p < 8; p++) acc[r][p] = bb;
        }
        #pragma unroll 4
        for (int ee = 0; ee < 128; ee++) {
            const float4 w1v = *(const float4*)&W1s[ee * 128 + e4];
            u64 dw[4];
            dw[0] = dup2(w1v.x); dw[1] = dup2(w1v.y);
            dw[2] = dup2(w1v.z); dw[3] = dup2(w1v.w);
            const int sw = (ee >> 2) & 7;
            u64 x[8];
            #pragma unroll
            for (int jj = 0; jj < 4; jj++) {
                const ulonglong2 xc =
                    *(const ulonglong2*)&xsT[ee * 128 + ((tg * 4 + jj) ^ sw) * 4];
                x[2 * jj] = xc.x; x[2 * jj + 1] = xc.y;
            }
            #pragma unroll
            for (int r = 0; r < 4; r++)
                #pragma unroll
                for (int p = 0; p < 8; p++) fma2(acc[r][p], dw[r], x[p]);
        }

        // epilogue: out[t] = b2 + sum_j relu(h[t][j]) * W2[j]
        {
            const float w2a = W2s[e4], w2b = W2s[e4 + 1];
            const float w2c = W2s[e4 + 2], w2d = W2s[e4 + 3];
            float v[16];
            #pragma unroll
            for (int p = 0; p < 8; p++) {
                const float2 h0 = unpk(acc[0][p]);
                const float2 h1 = unpk(acc[1][p]);
                const float2 h2 = unpk(acc[2][p]);
                const float2 h3 = unpk(acc[3][p]);
                v[2 * p]     = fmaxf(h0.x, 0.f) * w2a + fmaxf(h1.x, 0.f) * w2b
                             + fmaxf(h2.x, 0.f) * w2c + fmaxf(h3.x, 0.f) * w2d;
                v[2 * p + 1] = fmaxf(h0.y, 0.f) * w2a + fmaxf(h1.y, 0.f) * w2b
                             + fmaxf(h2.y, 0.f) * w2c + fmaxf(h3.y, 0.f) * w2d;
            }
            // full j-reduction: one warp covers all 128 j -> butterfly over lanes
            #pragma unroll
            for (int k = 0; k < 16; k++) {
                v[k] += __shfl_xor_sync(0xffffffffu, v[k], 16);
                v[k] += __shfl_xor_sync(0xffffffffu, v[k], 8);
                v[k] += __shfl_xor_sync(0xffffffffu, v[k], 4);
                v[k] += __shfl_xor_sync(0xffffffffu, v[k], 2);
                v[k] += __shfl_xor_sync(0xffffffffu, v[k], 1);
            }
            float myv = v[0];
            #pragma unroll
            for (int k = 1; k < 16; k++) myv = (lane == k) ? v[k] : myv;
            if (lane < 16)
                out[(size_t)b * GSZ + g0 + t0 + lane] = myv + b2v;
        }
        // next tile's phase1 writes wT only; its reads/writes are ordered by
        // the two barriers above plus the phase1->phase2 barrier.
    }
}

extern "C" void kernel_launch(void* const* d_in, const int* in_sizes, int n_in,
                              void* d_out, int out_size)
{
    const float* pos     = (const float*)d_in[0];
    const float* feat    = (const float*)d_in[1];
    const float* origin  = (const float*)d_in[2];
    const float* lattice = (const float*)d_in[3];
    const float* scale   = (const float*)d_in[4];
    const float* W1      = (const float*)d_in[5];
    const float* b1      = (const float*)d_in[6];
    const float* W2      = (const float*)d_in[7];
    const float* b2      = (const float*)d_in[8];
    const int*   bn      = (const int*)  d_in[9];

    float* out  = (float*)d_out;                  // [B,48,48,48]
    float* cout = out + (size_t)4 * GSZ;          // [B,48,48,48,128]

    cudaFuncSetAttribute(dgnn2_kernel,
                         cudaFuncAttributeMaxDynamicSharedMemorySize, SMEM_BYTES);

    dgnn2_kernel<<<NBLK, THREADS, SMEM_BYTES>>>(
        pos, feat, origin, lattice, scale, W1, b1, W2, b2, bn, out, cout);
}

// round 3
// speedup vs baseline: 2.3090x; 1.0950x over previous
#include <cuda_runtime.h>

#define NX      48
#define GSZ     (48*48*48)        // 110592
#define TP      128               // grid points per tile
#define THREADS 512
#define NBLK    148
#define TILES_PER_B (GSZ/TP)      // 864
#define BLKS_PER_B  (NBLK/4)      // 37

typedef unsigned long long u64;

// Shared layout (floats), all 16B aligned:
// Fs   [64][128]      8192   (one batch's features)
// W1s  [128][128]     16384
// wT   [64][128]      8192   (weights, [n][t])
// xsT  [128][128]     16384  (x transposed, 16B-chunk XOR swizzle along t)
// b1s 128, W2s 128, poss 192, orgb 4, stpb 4
#define SM_FLOATS (8192 + 16384 + 8192 + 16384 + 128 + 128 + 192 + 8)
#define SMEM_BYTES (SM_FLOATS * 4)

__device__ __forceinline__ u64 dup2(float f) {
    u64 r; asm("mov.b64 %0, {%1, %1};" : "=l"(r) : "f"(f)); return r;
}
__device__ __forceinline__ void fma2(u64 &d, u64 a, u64 b) {
    asm("fma.rn.f32x2 %0, %1, %2, %0;" : "+l"(d) : "l"(a), "l"(b));
}
__device__ __forceinline__ float2 unpk(u64 v) {
    float2 r; asm("mov.b64 {%0, %1}, %2;" : "=f"(r.x), "=f"(r.y) : "l"(v)); return r;
}

__global__ void __launch_bounds__(THREADS, 1)
dgnn3_kernel(const float* __restrict__ pos,
             const float* __restrict__ feat,
             const float* __restrict__ origin,
             const float* __restrict__ lattice,
             const float* __restrict__ scale_p,
             const float* __restrict__ W1,
             const float* __restrict__ b1,
             const float* __restrict__ W2,
             const float* __restrict__ b2_p,
             const int*   __restrict__ bnodes,
             float* __restrict__ out,
             float* __restrict__ cout)
{
    extern __shared__ float sm[];
    float* Fs   = sm;                  // [n][e]
    float* W1s  = Fs   + 8192;         // [ee][j]
    float* wT   = W1s  + 16384;        // [n][t]
    float* xsT  = wT   + 8192;         // [e][t] (swizzled 16B chunks)
    float* b1s  = xsT  + 16384;
    float* W2s  = b1s  + 128;
    float* poss = W2s  + 128;          // [n][3]
    float* orgb = poss + 192;          // [3]
    float* stpb = orgb + 4;            // [3]

    const int tid = threadIdx.x;
    const int b   = blockIdx.x & 3;    // batch for this block
    const int qb  = blockIdx.x >> 2;   // block index within batch (0..36)

    // ---- one-time preload ----
    for (int i = tid; i < 2048; i += THREADS)
        ((float4*)Fs)[i] = ((const float4*)(feat + b * 8192))[i];
    for (int i = tid; i < 4096; i += THREADS)
        ((float4*)W1s)[i] = ((const float4*)W1)[i];
    if (tid < 128) { b1s[tid] = b1[tid]; W2s[tid] = W2[tid]; }
    if (tid < 192) poss[tid] = pos[b * 192 + tid];
    if (tid < 3) {
        orgb[tid] = origin[b * 3 + tid];
        stpb[tid] = lattice[b * 9 + tid * 4] * (1.0f / 47.0f);
    }
    const float s   = scale_p[0];
    const float s2  = s * s;
    const float b2v = b2_p[0];
    const int   bn  = bnodes[b];
    const int   nEnd = (bn + 3) & ~3;   // phase-2 loop bound (uniform per block)
    __syncthreads();

    const int lane = tid & 31;
    const int e4   = lane * 4;         // column base (E in phase2, J in phase3)
    const int tg   = tid >> 5;         // warp id 0..15
    const int t0   = tg * 8;           // 8 grid points per warp/thread
    const int swz2 = lane & 7;         // (e>>2)&7 for this thread's 4 rows

    for (int tile = qb; tile < TILES_PER_B; tile += BLKS_PER_B) {
        const int g0 = tile * TP;

        // ================= phase 1: Lorentzian weights wT[n][t] =============
        {
            const int t  = tid & 127;          // grid point
            const int ng = (tid >> 7) * 16;    // 16-atom slab
            const int g  = g0 + t;
            const int ix = g / 2304;
            const int rm = g - ix * 2304;
            const int iy = rm / 48;
            const int iz = rm - iy * 48;
            const float gx = orgb[0] + (float)ix * stpb[0];
            const float gy = orgb[1] + (float)iy * stpb[1];
            const float gz = orgb[2] + (float)iz * stpb[2];
            #pragma unroll 4
            for (int k = 0; k < 16; k++) {
                const int n = ng + k;
                const float dx = gx - poss[n * 3 + 0];
                const float dy = gy - poss[n * 3 + 1];
                const float dz = gz - poss[n * 3 + 2];
                const float d2 = dx * dx + dy * dy + dz * dz;
                wT[n * 128 + t] = (n < bn) ? __fdividef(s, s2 + d2) : 0.0f;
            }
        }
        __syncthreads();

        // ================= phase 2: x[t][e] = sum_n w[n][t] * F[n][e] ========
        u64 acc[4][4];
        #pragma unroll
        for (int r = 0; r < 4; r++)
            #pragma unroll
            for (int p = 0; p < 4; p++) acc[r][p] = 0ull;

        #pragma unroll 4
        for (int n = 0; n < nEnd; n++) {
            const float4 f = *(const float4*)&Fs[n * 128 + e4];
            u64 df[4];
            df[0] = dup2(f.x); df[1] = dup2(f.y);
            df[2] = dup2(f.z); df[3] = dup2(f.w);
            const ulonglong2* wp = (const ulonglong2*)&wT[n * 128 + t0];
            const ulonglong2 wa = wp[0], wb = wp[1];
            const u64 w[4] = {wa.x, wa.y, wb.x, wb.y};
            #pragma unroll
            for (int r = 0; r < 4; r++)
                #pragma unroll
                for (int p = 0; p < 4; p++) fma2(acc[r][p], df[r], w[p]);
        }

        // write xsT (swizzled 16B chunks) + cout (coalesced float4 over e)
        #pragma unroll
        for (int r = 0; r < 4; r++) {
            #pragma unroll
            for (int jj = 0; jj < 2; jj++) {
                const int c = (tg * 2 + jj) ^ swz2;
                ulonglong2 v; v.x = acc[r][2 * jj]; v.y = acc[r][2 * jj + 1];
                *(ulonglong2*)&xsT[(e4 + r) * 128 + c * 4] = v;
            }
        }
        {
            const size_t base = ((size_t)b * GSZ + g0) * 128 + e4;
            #pragma unroll
            for (int p = 0; p < 4; p++) {
                const float2 a0 = unpk(acc[0][p]);
                const float2 a1 = unpk(acc[1][p]);
                const float2 a2 = unpk(acc[2][p]);
                const float2 a3 = unpk(acc[3][p]);
                float4 v0 = make_float4(a0.x, a1.x, a2.x, a3.x);
                float4 v1 = make_float4(a0.y, a1.y, a2.y, a3.y);
                *(float4*)&cout[base + (size_t)(t0 + 2 * p) * 128]     = v0;
                *(float4*)&cout[base + (size_t)(t0 + 2 * p + 1) * 128] = v1;
            }
        }
        __syncthreads();

        // ================= phase 3: h[t][j] = relu(b1 + sum_e x*W1) ==========
        #pragma unroll
        for (int r = 0; r < 4; r++) {
            const u64 bb = dup2(b1s[e4 + r]);
            #pragma unroll
            for (int p = 0; p < 4; p++) acc[r][p] = bb;
        }
        #pragma unroll 4
        for (int ee = 0; ee < 128; ee++) {
            const float4 w1v = *(const float4*)&W1s[ee * 128 + e4];
            u64 dw[4];
            dw[0] = dup2(w1v.x); dw[1] = dup2(w1v.y);
            dw[2] = dup2(w1v.z); dw[3] = dup2(w1v.w);
            const int sw = (ee >> 2) & 7;
            u64 x[4];
            #pragma unroll
            for (int jj = 0; jj < 2; jj++) {
                const ulonglong2 xc =
                    *(const ulonglong2*)&xsT[ee * 128 + ((tg * 2 + jj) ^ sw) * 4];
                x[2 * jj] = xc.x; x[2 * jj + 1] = xc.y;
            }
            #pragma unroll
            for (int r = 0; r < 4; r++)
                #pragma unroll
                for (int p = 0; p < 4; p++) fma2(acc[r][p], dw[r], x[p]);
        }

        // epilogue: out[t] = b2 + sum_j relu(h[t][j]) * W2[j]
        {
            const float w2a = W2s[e4], w2b = W2s[e4 + 1];
            const float w2c = W2s[e4 + 2], w2d = W2s[e4 + 3];
            float v[8];
            #pragma unroll
            for (int p = 0; p < 4; p++) {
                const float2 h0 = unpk(acc[0][p]);
                const float2 h1 = unpk(acc[1][p]);
                const float2 h2 = unpk(acc[2][p]);
                const float2 h3 = unpk(acc[3][p]);
                v[2 * p]     = fmaxf(h0.x, 0.f) * w2a + fmaxf(h1.x, 0.f) * w2b
                             + fmaxf(h2.x, 0.f) * w2c + fmaxf(h3.x, 0.f) * w2d;
                v[2 * p + 1] = fmaxf(h0.y, 0.f) * w2a + fmaxf(h1.y, 0.f) * w2b
                             + fmaxf(h2.y, 0.f) * w2c + fmaxf(h3.y, 0.f) * w2d;
            }
            // full j-reduction across the warp (covers all 128 j)
            #pragma unroll
            for (int k = 0; k < 8; k++) {
                v[k] += __shfl_xor_sync(0xffffffffu, v[k], 16);
                v[k] += __shfl_xor_sync(0xffffffffu, v[k], 8);
                v[k] += __shfl_xor_sync(0xffffffffu, v[k], 4);
                v[k] += __shfl_xor_sync(0xffffffffu, v[k], 2);
                v[k] += __shfl_xor_sync(0xffffffffu, v[k], 1);
            }
            float myv = v[0];
            #pragma unroll
            for (int k = 1; k < 8; k++) myv = (lane == k) ? v[k] : myv;
            if (lane < 8)
                out[(size_t)b * GSZ + g0 + t0 + lane] = myv + b2v;
        }
        // next tile's phase1 writes wT only; ordered by the barriers above.
    }
}

extern "C" void kernel_launch(void* const* d_in, const int* in_sizes, int n_in,
                              void* d_out, int out_size)
{
    const float* pos     = (const float*)d_in[0];
    const float* feat    = (const float*)d_in[1];
    const float* origin  = (const float*)d_in[2];
    const float* lattice = (const float*)d_in[3];
    const float* scale   = (const float*)d_in[4];
    const float* W1      = (const float*)d_in[5];
    const float* b1      = (const float*)d_in[6];
    const float* W2      = (const float*)d_in[7];
    const float* b2      = (const float*)d_in[8];
    const int*   bn      = (const int*)  d_in[9];

    float* out  = (float*)d_out;                  // [B,48,48,48]
    float* cout = out + (size_t)4 * GSZ;          // [B,48,48,48,128]

    cudaFuncSetAttribute(dgnn3_kernel,
                         cudaFuncAttributeMaxDynamicSharedMemorySize, SMEM_BYTES);

    dgnn3_kernel<<<NBLK, THREADS, SMEM_BYTES>>>(
        pos, feat, origin, lattice, scale, W1, b1, W2, b2, bn, out, cout);
}

// round 4
// speedup vs baseline: 4.4281x; 1.9177x over previous
#include <cuda_runtime.h>

#define NX      48
#define GSZ     (48*48*48)        // 110592
#define TP      128               // grid points per tile
#define THREADS 512
#define NBLK    148
#define TILES_PER_B (GSZ/TP)      // 864

typedef unsigned long long u64;

// Precomputed FW = F @ W1 per batch: [4][64][128]
__device__ float FWg[4 * 64 * 128];

// Shared layout (floats):
// Fs  [64][128] 8192, FWs [64][128] 8192, wT [64][128] 8192,
// b1s 128, W2s 128, poss 192, orgb 4, stpb 4
#define SM_FLOATS (8192 + 8192 + 8192 + 128 + 128 + 192 + 8)
#define SMEM_BYTES (SM_FLOATS * 4)

__device__ __forceinline__ u64 dup2(float f) {
    u64 r; asm("mov.b64 %0, {%1, %1};" : "=l"(r) : "f"(f)); return r;
}
__device__ __forceinline__ void fma2(u64 &d, u64 a, u64 b) {
    asm("fma.rn.f32x2 %0, %1, %2, %0;" : "+l"(d) : "l"(a), "l"(b));
}
__device__ __forceinline__ float2 unpk(u64 v) {
    float2 r; asm("mov.b64 {%0, %1}, %2;" : "=f"(r.x), "=f"(r.y) : "l"(v)); return r;
}

// ---------------- prep: FW[b][n][j] = sum_e F[b][n][e] * W1[e][j] ----------
__global__ void __launch_bounds__(256, 1)
prep_kernel(const float* __restrict__ feat, const float* __restrict__ W1)
{
    const int task = blockIdx.x * 256 + threadIdx.x;   // 8192 tasks
    const int j4   = (task & 31) * 4;
    const int bn_  = task >> 5;                        // b*64+n, 0..255
    const float* frow = feat + (size_t)bn_ * 128;
    float4 acc = make_float4(0.f, 0.f, 0.f, 0.f);
    #pragma unroll 8
    for (int e = 0; e < 128; e++) {
        const float  fv = __ldg(frow + e);
        const float4 wv = __ldg((const float4*)(W1 + e * 128 + j4));
        acc.x += fv * wv.x; acc.y += fv * wv.y;
        acc.z += fv * wv.z; acc.w += fv * wv.w;
    }
    *(float4*)&FWg[(size_t)bn_ * 128 + j4] = acc;
}

// ---------------- main ------------------------------------------------------
__global__ void __launch_bounds__(THREADS, 1)
dgnn4_kernel(const float* __restrict__ pos,
             const float* __restrict__ feat,
             const float* __restrict__ origin,
             const float* __restrict__ lattice,
             const float* __restrict__ scale_p,
             const float* __restrict__ b1,
             const float* __restrict__ W2,
             const float* __restrict__ b2_p,
             const int*   __restrict__ bnodes,
             float* __restrict__ out,
             float* __restrict__ cout)
{
    extern __shared__ float sm[];
    float* Fs   = sm;                  // [n][e]
    float* FWs  = Fs   + 8192;         // [n][j]
    float* wT   = FWs  + 8192;         // [n][t]
    float* b1s  = wT   + 8192;
    float* W2s  = b1s  + 128;
    float* poss = W2s  + 128;          // [n][3]
    float* orgb = poss + 192;
    float* stpb = orgb + 4;

    const int tid = threadIdx.x;

    // ---- deterministic proportional block->batch allocation ----
    int bn4[4], wgt[4];
    int wsum = 0;
    #pragma unroll
    for (int i = 0; i < 4; i++) {
        bn4[i] = bnodes[i];
        int ne = (bn4[i] + 3) & ~3;
        wgt[i] = ne + 4;               // +4 ~ fixed per-tile overhead
        wsum  += wgt[i];
    }
    int bnd[5]; bnd[0] = 0;
    {
        int cum = 0;
        #pragma unroll
        for (int i = 0; i < 4; i++) {
            cum += wgt[i];
            bnd[i + 1] = (2 * NBLK * cum + wsum) / (2 * wsum);  // rounded
        }
    }
    int b = 0;
    while (b < 3 && (int)blockIdx.x >= bnd[b + 1]) b++;
    const int rank = blockIdx.x - bnd[b];
    const int nblk = bnd[b + 1] - bnd[b];
    const int bn   = bn4[b];
    const int nEnd = (bn + 3) & ~3;

    // ---- one-time preload ----
    for (int i = tid; i < 2048; i += THREADS)
        ((float4*)Fs)[i] = ((const float4*)(feat + b * 8192))[i];
    for (int i = tid; i < 2048; i += THREADS)
        ((float4*)FWs)[i] = ((const float4*)(FWg + b * 8192))[i];
    if (tid < 128) { b1s[tid] = b1[tid]; W2s[tid] = W2[tid]; }
    if (tid < 192) poss[tid] = pos[b * 192 + tid];
    if (tid < 3) {
        orgb[tid] = origin[b * 3 + tid];
        stpb[tid] = lattice[b * 9 + tid * 4] * (1.0f / 47.0f);
    }
    const float s   = scale_p[0];
    const float s2  = s * s;
    const float b2v = b2_p[0];
    __syncthreads();

    const int lane = tid & 31;
    const int e4   = lane * 4;         // covers e (and j) columns per warp
    const int tg   = tid >> 5;         // warp id 0..15
    const int t0   = tg * 8;           // 8 grid points per warp

    for (int tile = rank; tile < TILES_PER_B; tile += nblk) {
        const int g0 = tile * TP;

        // ====== phase 1: Lorentzian weights wT[n][t], n < nEnd ======
        {
            const int t    = tid & 127;
            const int slab = (tid >> 7) * 16;
            if (slab < nEnd) {
                const int g  = g0 + t;
                const int ix = g / 2304;
                const int rm = g - ix * 2304;
                const int iy = rm / 48;
                const int iz = rm - iy * 48;
                const float gx = orgb[0] + (float)ix * stpb[0];
                const float gy = orgb[1] + (float)iy * stpb[1];
                const float gz = orgb[2] + (float)iz * stpb[2];
                const int kmax = min(16, nEnd - slab);
                for (int k = 0; k < kmax; k++) {
                    const int n = slab + k;
                    const float dx = gx - poss[n * 3 + 0];
                    const float dy = gy - poss[n * 3 + 1];
                    const float dz = gz - poss[n * 3 + 2];
                    const float d2 = dx * dx + dy * dy + dz * dz;
                    wT[n * 128 + t] = (n < bn) ? __fdividef(s, s2 + d2) : 0.0f;
                }
            }
        }
        __syncthreads();

        // ====== fused phase 2: x and h in one n-loop ======
        u64 ax[4][4], ah[4][4];
        #pragma unroll
        for (int r = 0; r < 4; r++) {
            const u64 bb = dup2(b1s[e4 + r]);
            #pragma unroll
            for (int p = 0; p < 4; p++) { ax[r][p] = 0ull; ah[r][p] = bb; }
        }

        #pragma unroll 2
        for (int n = 0; n < nEnd; n++) {
            const float4 f  = *(const float4*)&Fs[n * 128 + e4];
            const float4 fw = *(const float4*)&FWs[n * 128 + e4];
            u64 df[4], dh[4];
            df[0] = dup2(f.x);  df[1] = dup2(f.y);
            df[2] = dup2(f.z);  df[3] = dup2(f.w);
            dh[0] = dup2(fw.x); dh[1] = dup2(fw.y);
            dh[2] = dup2(fw.z); dh[3] = dup2(fw.w);
            const ulonglong2* wp = (const ulonglong2*)&wT[n * 128 + t0];
            const ulonglong2 wa = wp[0], wb = wp[1];
            const u64 w[4] = {wa.x, wa.y, wb.x, wb.y};
            #pragma unroll
            for (int r = 0; r < 4; r++)
                #pragma unroll
                for (int p = 0; p < 4; p++) {
                    fma2(ax[r][p], df[r], w[p]);
                    fma2(ah[r][p], dh[r], w[p]);
                }
        }

        // cout: coalesced float4 over e
        {
            const size_t base = ((size_t)b * GSZ + g0) * 128 + e4;
            #pragma unroll
            for (int p = 0; p < 4; p++) {
                const float2 a0 = unpk(ax[0][p]);
                const float2 a1 = unpk(ax[1][p]);
                const float2 a2 = unpk(ax[2][p]);
                const float2 a3 = unpk(ax[3][p]);
                float4 v0 = make_float4(a0.x, a1.x, a2.x, a3.x);
                float4 v1 = make_float4(a0.y, a1.y, a2.y, a3.y);
                *(float4*)&cout[base + (size_t)(t0 + 2 * p) * 128]     = v0;
                *(float4*)&cout[base + (size_t)(t0 + 2 * p + 1) * 128] = v1;
            }
        }

        // epilogue: out[t] = b2 + sum_j relu(h[t][j]) * W2[j]
        {
            const float w2a = W2s[e4],     w2b = W2s[e4 + 1];
            const float w2c = W2s[e4 + 2], w2d = W2s[e4 + 3];
            float v[8];
            #pragma unroll
            for (int p = 0; p < 4; p++) {
                const float2 h0 = unpk(ah[0][p]);
                const float2 h1 = unpk(ah[1][p]);
                const float2 h2 = unpk(ah[2][p]);
                const float2 h3 = unpk(ah[3][p]);
                v[2 * p]     = fmaxf(h0.x, 0.f) * w2a + fmaxf(h1.x, 0.f) * w2b
                             + fmaxf(h2.x, 0.f) * w2c + fmaxf(h3.x, 0.f) * w2d;
                v[2 * p + 1] = fmaxf(h0.y, 0.f) * w2a + fmaxf(h1.y, 0.f) * w2b
                             + fmaxf(h2.y, 0.f) * w2c + fmaxf(h3.y, 0.f) * w2d;
            }
            #pragma unroll
            for (int k = 0; k < 8; k++) {
                v[k] += __shfl_xor_sync(0xffffffffu, v[k], 16);
                v[k] += __shfl_xor_sync(0xffffffffu, v[k], 8);
                v[k] += __shfl_xor_sync(0xffffffffu, v[k], 4);
                v[k] += __shfl_xor_sync(0xffffffffu, v[k], 2);
                v[k] += __shfl_xor_sync(0xffffffffu, v[k], 1);
            }
            float myv = v[0];
            #pragma unroll
            for (int k = 1; k < 8; k++) myv = (lane == k) ? v[k] : myv;
            if (lane < 8)
                out[(size_t)b * GSZ + g0 + t0 + lane] = myv + b2v;
        }
        __syncthreads();   // protect wT before next tile's phase 1
    }
}

extern "C" void kernel_launch(void* const* d_in, const int* in_sizes, int n_in,
                              void* d_out, int out_size)
{
    const float* pos     = (const float*)d_in[0];
    const float* feat    = (const float*)d_in[1];
    const float* origin  = (const float*)d_in[2];
    const float* lattice = (const float*)d_in[3];
    const float* scale   = (const float*)d_in[4];
    const float* W1      = (const float*)d_in[5];
    const float* b1      = (const float*)d_in[6];
    const float* W2      = (const float*)d_in[7];
    const float* b2      = (const float*)d_in[8];
    const int*   bn      = (const int*)  d_in[9];

    float* out  = (float*)d_out;                  // [B,48,48,48]
    float* cout = out + (size_t)4 * GSZ;          // [B,48,48,48,128]

    prep_kernel<<<32, 256>>>(feat, W1);

    cudaFuncSetAttribute(dgnn4_kernel,
                         cudaFuncAttributeMaxDynamicSharedMemorySize, SMEM_BYTES);
    dgnn4_kernel<<<NBLK, THREADS, SMEM_BYTES>>>(
        pos, feat, origin, lattice, scale, b1, W2, b2, bn, out, cout);
}

// round 6
// speedup vs baseline: 5.0141x; 1.1324x over previous
#include <cuda_runtime.h>
#include <cstdint>

#define GSZ     (48*48*48)        // 110592
#define TP      128
#define THREADS 512
#define NBLK    148
#define TILES_PER_B (GSZ/TP)      // 864
#define WST     66                // wbuf row stride (floats)

// smem float offsets
#define OFF_BH  0                 // u64[4][32][32]  -> 8192 floats
#define OFF_BL  8192              // 8192 floats
#define OFF_WB  16384             // 128*66 = 8448 floats
#define OFF_B1  24832             // 128
#define OFF_W2  24960             // 128
#define OFF_POS 25088             // 192
#define OFF_ORG 25280             // 4
#define OFF_STP 25284             // 4
#define SMEM_BYTES (25344 * 4)    // ~101 KB

__device__ float FWg[4 * 64 * 128];

// ---- helpers ----
__device__ __forceinline__ void mma16816(float c[4], const unsigned a[4],
                                         unsigned b0, unsigned b1) {
    asm volatile(
        "mma.sync.aligned.m16n8k16.row.col.f32.bf16.bf16.f32 "
        "{%0,%1,%2,%3}, {%4,%5,%6,%7}, {%8,%9}, {%0,%1,%2,%3};"
        : "+f"(c[0]), "+f"(c[1]), "+f"(c[2]), "+f"(c[3])
        : "r"(a[0]), "r"(a[1]), "r"(a[2]), "r"(a[3]), "r"(b0), "r"(b1));
}
// pack (f0,f1) -> bf16x2 hi + bf16x2 residual-lo
__device__ __forceinline__ void split_pair(float f0, float f1,
                                           unsigned &h, unsigned &l) {
    asm("cvt.rn.bf16x2.f32 %0, %1, %2;" : "=r"(h) : "f"(f1), "f"(f0));
    const float f0h = __uint_as_float(h << 16);
    const float f1h = __uint_as_float(h & 0xFFFF0000u);
    asm("cvt.rn.bf16x2.f32 %0, %1, %2;" : "=r"(l) : "f"(f1 - f1h), "f"(f0 - f0h));
}

// ---------------- prep: FW[b][n][j] = sum_e F[b][n][e] * W1[e][j] ----------
__global__ void __launch_bounds__(256, 1)
prep_kernel(const float* __restrict__ feat, const float* __restrict__ W1)
{
    const int task = blockIdx.x * 256 + threadIdx.x;   // 8192
    const int j4   = (task & 31) * 4;
    const int bn_  = task >> 5;
    const float* frow = feat + (size_t)bn_ * 128;
    float4 acc = make_float4(0.f, 0.f, 0.f, 0.f);
    #pragma unroll 8
    for (int e = 0; e < 128; e++) {
        const float  fv = __ldg(frow + e);
        const float4 wv = __ldg((const float4*)(W1 + e * 128 + j4));
        acc.x += fv * wv.x; acc.y += fv * wv.y;
        acc.z += fv * wv.z; acc.w += fv * wv.w;
    }
    *(float4*)&FWg[(size_t)bn_ * 128 + j4] = acc;
}

// ---------------- main ------------------------------------------------------
__global__ void __launch_bounds__(THREADS, 1)
dgnn6_kernel(const float* __restrict__ pos,
             const float* __restrict__ feat,
             const float* __restrict__ origin,
             const float* __restrict__ lattice,
             const float* __restrict__ scale_p,
             const float* __restrict__ b1,
             const float* __restrict__ W2,
             const float* __restrict__ b2_p,
             const int*   __restrict__ bnodes,
             float* __restrict__ out,
             float* __restrict__ cout)
{
    extern __shared__ float sm[];
    unsigned long long* Bh = (unsigned long long*)(sm + OFF_BH); // [ks*32+ctg][lane]
    unsigned long long* Bl = (unsigned long long*)(sm + OFF_BL);
    float* wbuf = sm + OFF_WB;     // [t][WST]
    float* b1s  = sm + OFF_B1;
    float* W2s  = sm + OFF_W2;
    float* poss = sm + OFF_POS;
    float* orgb = sm + OFF_ORG;
    float* stpb = sm + OFF_STP;

    const int tid  = threadIdx.x;
    const int wid  = tid >> 5;
    const int lane = tid & 31;

    // ---- block -> batch allocation (weight ~ per-tile cost) ----
    int bn4[4], wgt[4], wsum = 0;
    #pragma unroll
    for (int i = 0; i < 4; i++) {
        bn4[i] = bnodes[i];
        wgt[i] = 3 * ((bn4[i] + 15) >> 4) + 2;
        wsum  += wgt[i];
    }
    int bnd[5]; bnd[0] = 0;
    { int cum = 0;
      #pragma unroll
      for (int i = 0; i < 4; i++) { cum += wgt[i];
          bnd[i + 1] = (2 * NBLK * cum + wsum) / (2 * wsum); } }
    int b = 0;
    while (b < 3 && (int)blockIdx.x >= bnd[b + 1]) b++;
    const int rank   = blockIdx.x - bnd[b];
    const int nblk   = bnd[b + 1] - bnd[b];
    const int bn     = bn4[b];
    const int kSteps = (bn + 15) >> 4;

    // ---- prologue: constants ----
    if (tid < 128) { b1s[tid] = b1[tid]; W2s[tid] = W2[tid]; }
    if (tid < 192) poss[tid] = pos[b * 192 + tid];
    if (tid < 3) {
        orgb[tid] = origin[b * 3 + tid];
        stpb[tid] = lattice[b * 9 + tid * 4] * (1.0f / 47.0f);
    }
    const float s   = scale_p[0];
    const float s2  = s * s;
    const float b2v = b2_p[0];

    // ---- B fragments (once per block): B[k=atom][col] = [F | FW] ----
    // frag: b32 = {bf16(B[k0,col]), bf16(B[k0+1,col])}, u64 = {reg0(k0..k0+1), reg1(k0+8..k0+9)}
    for (int task = tid; task < 4096; task += THREADS) {
        const int ln  = task & 31;
        const int ctg = (task >> 5) & 31;
        const int ks  = task >> 10;
        const int col = ctg * 8 + (ln >> 2);
        const int k0  = ks * 16 + (ln & 3) * 2;
        const float* src = (col < 128)
            ? (feat + (size_t)b * 8192 + col)
            : (FWg + (size_t)b * 8192 + (col - 128));
        const float f0 = __ldg(src + (size_t)k0 * 128);
        const float f1 = __ldg(src + (size_t)(k0 + 1) * 128);
        const float f2 = __ldg(src + (size_t)(k0 + 8) * 128);
        const float f3 = __ldg(src + (size_t)(k0 + 9) * 128);
        unsigned h0, l0, h1, l1;
        split_pair(f0, f1, h0, l0);
        split_pair(f2, f3, h1, l1);
        Bh[(ks * 32 + ctg) * 32 + ln] = (unsigned long long)h0 | ((unsigned long long)h1 << 32);
        Bl[(ks * 32 + ctg) * 32 + ln] = (unsigned long long)l0 | ((unsigned long long)l1 << 32);
    }
    __syncthreads();

    const int tg   = wid & 7;      // t-group: rows tg*16 .. tg*16+15
    const int cg   = wid >> 3;     // 0: x-cols (e), 1: h-cols (j)
    const int row0 = tg * 16 + (lane >> 2);
    const int qk   = (lane & 3) * 2;

    for (int tile = rank; tile < TILES_PER_B; tile += nblk) {
        const int g0 = tile * TP;

        // ===== phase 1: w[t][n] fp32 into wbuf =====
        {
            const int t    = tid & 127;
            const int slab = (tid >> 7) << 4;
            if (slab < kSteps * 16) {
                const int g  = g0 + t;
                const int ix = g / 2304;
                const int rm = g - ix * 2304;
                const int iy = rm / 48;
                const int iz = rm - iy * 48;
                const float gx = orgb[0] + (float)ix * stpb[0];
                const float gy = orgb[1] + (float)iy * stpb[1];
                const float gz = orgb[2] + (float)iz * stpb[2];
                #pragma unroll
                for (int k = 0; k < 16; k++) {
                    const int n = slab + k;
                    const float dx = gx - poss[n * 3 + 0];
                    const float dy = gy - poss[n * 3 + 1];
                    const float dz = gz - poss[n * 3 + 2];
                    const float d2 = dx * dx + dy * dy + dz * dz;
                    wbuf[t * WST + n] = (n < bn) ? __fdividef(s, s2 + d2) : 0.0f;
                }
            }
        }
        __syncthreads();

        // ===== A fragments (bf16 hi/lo) from wbuf =====
        unsigned aH[4][4], aL[4][4];
        #pragma unroll
        for (int ks = 0; ks < 4; ks++) if (ks < kSteps) {
            const float* w0 = wbuf + row0 * WST + ks * 16 + qk;
            const float* w8 = wbuf + (row0 + 8) * WST + ks * 16 + qk;
            const float2 p0 = *(const float2*)(w0);
            const float2 p1 = *(const float2*)(w8);
            const float2 p2 = *(const float2*)(w0 + 8);
            const float2 p3 = *(const float2*)(w8 + 8);
            split_pair(p0.x, p0.y, aH[ks][0], aL[ks][0]);
            split_pair(p1.x, p1.y, aH[ks][1], aL[ks][1]);
            split_pair(p2.x, p2.y, aH[ks][2], aL[ks][2]);
            split_pair(p3.x, p3.y, aH[ks][3], aL[ks][3]);
        }

        // ===== GEMM: c[ct][4] over 16 col-tiles of this half =====
        float c[16][4];
        #pragma unroll
        for (int ct = 0; ct < 16; ct++)
            #pragma unroll
            for (int r = 0; r < 4; r++) c[ct][r] = 0.f;

        #pragma unroll
        for (int ct = 0; ct < 16; ct++) {
            const int gct = cg * 16 + ct;
            #pragma unroll
            for (int ks = 0; ks < 4; ks++) if (ks < kSteps) {
                const unsigned long long bh = Bh[(ks * 32 + gct) * 32 + lane];
                const unsigned long long bl = Bl[(ks * 32 + gct) * 32 + lane];
                const unsigned bh0 = (unsigned)bh, bh1 = (unsigned)(bh >> 32);
                const unsigned bl0 = (unsigned)bl, bl1 = (unsigned)(bl >> 32);
                mma16816(c[ct], aH[ks], bh0, bh1);
                mma16816(c[ct], aH[ks], bl0, bl1);
                mma16816(c[ct], aL[ks], bh0, bh1);
            }
        }

        // ===== epilogue =====
        if (cg == 0) {
            // x -> cout: c0,c1 = (row0, e0,e0+1); c2,c3 = (row0+8, ...)
            const size_t base = ((size_t)b * GSZ + g0) * 128;
            #pragma unroll
            for (int ct = 0; ct < 16; ct++) {
                const int e0 = ct * 8 + qk;
                *(float2*)&cout[base + (size_t)row0 * 128 + e0] =
                    make_float2(c[ct][0], c[ct][1]);
                *(float2*)&cout[base + (size_t)(row0 + 8) * 128 + e0] =
                    make_float2(c[ct][2], c[ct][3]);
            }
        } else {
            // h -> out: relu(h+b1)*W2, reduce over j
            float v0 = 0.f, v1 = 0.f;
            #pragma unroll
            for (int ct = 0; ct < 16; ct++) {
                const int j0 = ct * 8 + qk;
                const float b1a = b1s[j0], b1b = b1s[j0 + 1];
                const float w2a = W2s[j0], w2b = W2s[j0 + 1];
                v0 += fmaxf(c[ct][0] + b1a, 0.f) * w2a
                    + fmaxf(c[ct][1] + b1b, 0.f) * w2b;
                v1 += fmaxf(c[ct][2] + b1a, 0.f) * w2a
                    + fmaxf(c[ct][3] + b1b, 0.f) * w2b;
            }
            v0 += __shfl_xor_sync(0xffffffffu, v0, 1);
            v0 += __shfl_xor_sync(0xffffffffu, v0, 2);
            v1 += __shfl_xor_sync(0xffffffffu, v1, 1);
            v1 += __shfl_xor_sync(0xffffffffu, v1, 2);
            if ((lane & 3) == 0) {
                out[(size_t)b * GSZ + g0 + row0]     = v0 + b2v;
                out[(size_t)b * GSZ + g0 + row0 + 8] = v1 + b2v;
            }
        }
        __syncthreads();   // wbuf reused next tile
    }
}

extern "C" void kernel_launch(void* const* d_in, const int* in_sizes, int n_in,
                              void* d_out, int out_size)
{
    const float* pos     = (const float*)d_in[0];
    const float* feat    = (const float*)d_in[1];
    const float* origin  = (const float*)d_in[2];
    const float* lattice = (const float*)d_in[3];
    const float* scale   = (const float*)d_in[4];
    const float* W1      = (const float*)d_in[5];
    const float* b1      = (const float*)d_in[6];
    const float* W2      = (const float*)d_in[7];
    const float* b2      = (const float*)d_in[8];
    const int*   bn      = (const int*)  d_in[9];

    float* out  = (float*)d_out;                 // [B,48,48,48]
    float* cout = out + (size_t)4 * GSZ;         // [B,48,48,48,128]

    prep_kernel<<<32, 256>>>(feat, W1);

    cudaFuncSetAttribute(dgnn6_kernel,
                         cudaFuncAttributeMaxDynamicSharedMemorySize, SMEM_BYTES);
    dgnn6_kernel<<<NBLK, THREADS, SMEM_BYTES>>>(
        pos, feat, origin, lattice, scale, b1, W2, b2, bn, out, cout);
}

// round 7
// speedup vs baseline: 8.2236x; 1.6401x over previous
#include <cuda_runtime.h>
#include <cuda_fp16.h>
#include <cstdint>

#define GSZ     (48*48*48)        // 110592
#define TP      128
#define THREADS 512
#define NBLK    148
#define TILES_PER_B (GSZ/TP)      // 864
#define WST     36                // wbuf row stride in u32 (half2 units)

// smem float offsets
#define OFF_BHL 0                 // ulonglong2[4][32][32] = 16384 floats
#define OFF_WB0 16384             // 128*36 u32 = 4608
#define OFF_WB1 20992
#define OFF_B1  25600
#define OFF_W2  25728
#define OFF_POS 25856
#define OFF_ORG 26048
#define OFF_STP 26052
#define SMEM_BYTES (26112 * 4)    // ~102 KB

__device__ float FWg[4 * 64 * 128];

// ---- helpers ----
__device__ __forceinline__ void mma16816(float c[4], const unsigned a[4],
                                         unsigned b0, unsigned b1) {
    asm volatile(
        "mma.sync.aligned.m16n8k16.row.col.f32.f16.f16.f32 "
        "{%0,%1,%2,%3}, {%4,%5,%6,%7}, {%8,%9}, {%0,%1,%2,%3};"
        : "+f"(c[0]), "+f"(c[1]), "+f"(c[2]), "+f"(c[3])
        : "r"(a[0]), "r"(a[1]), "r"(a[2]), "r"(a[3]), "r"(b0), "r"(b1));
}
// (f0,f1) -> fp16x2 hi (lo half = f0) + fp16x2 residual
__device__ __forceinline__ void split_pair_h(float f0, float f1,
                                             unsigned &h, unsigned &l) {
    __half2 hh = __floats2half2_rn(f0, f1);
    h = *(unsigned*)&hh;
    float2 bk = __half22float2(hh);
    __half2 ll = __floats2half2_rn(f0 - bk.x, f1 - bk.y);
    l = *(unsigned*)&ll;
}

// ---------------- prep: FW[b][n][j] = sum_e F[b][n][e] * W1[e][j] ----------
__global__ void __launch_bounds__(256, 1)
prep_kernel(const float* __restrict__ feat, const float* __restrict__ W1)
{
    const int task = blockIdx.x * 256 + threadIdx.x;   // 8192
    const int j4   = (task & 31) * 4;
    const int bn_  = task >> 5;
    const float* frow = feat + (size_t)bn_ * 128;
    float4 acc = make_float4(0.f, 0.f, 0.f, 0.f);
    #pragma unroll 8
    for (int e = 0; e < 128; e++) {
        const float  fv = __ldg(frow + e);
        const float4 wv = __ldg((const float4*)(W1 + e * 128 + j4));
        acc.x += fv * wv.x; acc.y += fv * wv.y;
        acc.z += fv * wv.z; acc.w += fv * wv.w;
    }
    *(float4*)&FWg[(size_t)bn_ * 128 + j4] = acc;
}

// ---------------- main ------------------------------------------------------
__global__ void __launch_bounds__(THREADS, 1)
dgnn7_kernel(const float* __restrict__ pos,
             const float* __restrict__ feat,
             const float* __restrict__ origin,
             const float* __restrict__ lattice,
             const float* __restrict__ scale_p,
             const float* __restrict__ b1,
             const float* __restrict__ W2,
             const float* __restrict__ b2_p,
             const int*   __restrict__ bnodes,
             float* __restrict__ out,
             float* __restrict__ cout)
{
    extern __shared__ float sm[];
    ulonglong2* BHL = (ulonglong2*)(sm + OFF_BHL);   // [(ks*32+ctg)*32+lane] = {Bh, Bl}
    unsigned* wb[2] = { (unsigned*)(sm + OFF_WB0), (unsigned*)(sm + OFF_WB1) };
    float* b1s  = sm + OFF_B1;
    float* W2s  = sm + OFF_W2;
    float* poss = sm + OFF_POS;
    float* orgb = sm + OFF_ORG;
    float* stpb = sm + OFF_STP;

    const int tid  = threadIdx.x;
    const int wid  = tid >> 5;
    const int lane = tid & 31;

    // ---- block -> batch allocation (weight ~ per-tile cost) ----
    int bn4[4], wgt[4], wsum = 0;
    #pragma unroll
    for (int i = 0; i < 4; i++) {
        bn4[i] = bnodes[i];
        wgt[i] = 2 * ((bn4[i] + 15) >> 4) + 2;
        wsum  += wgt[i];
    }
    int bnd[5]; bnd[0] = 0;
    { int cum = 0;
      #pragma unroll
      for (int i = 0; i < 4; i++) { cum += wgt[i];
          bnd[i + 1] = (2 * NBLK * cum + wsum) / (2 * wsum); } }
    int b = 0;
    while (b < 3 && (int)blockIdx.x >= bnd[b + 1]) b++;
    const int rank   = blockIdx.x - bnd[b];
    const int nblk   = bnd[b + 1] - bnd[b];
    const int bn     = bn4[b];
    const int kSteps = (bn + 15) >> 4;

    // ---- prologue: constants ----
    if (tid < 128) { b1s[tid] = b1[tid]; W2s[tid] = W2[tid]; }
    if (tid < 192) poss[tid] = pos[b * 192 + tid];
    if (tid < 3) {
        orgb[tid] = origin[b * 3 + tid];
        stpb[tid] = lattice[b * 9 + tid * 4] * (1.0f / 47.0f);
    }
    const float s   = scale_p[0];
    const float s2  = s * s;
    const float b2v = b2_p[0];

    // ---- B fragments (once): B rows = [F | FW], fp16 hi + residual lo ----
    for (int task = tid; task < 4096; task += THREADS) {
        const int ln  = task & 31;
        const int ctg = (task >> 5) & 31;
        const int ks  = task >> 10;
        const int col = ctg * 8 + (ln >> 2);
        const int k0  = ks * 16 + (ln & 3) * 2;
        const float* src = (col < 128)
            ? (feat + (size_t)b * 8192 + col)
            : (FWg + (size_t)b * 8192 + (col - 128));
        const float f0 = __ldg(src + (size_t)k0 * 128);
        const float f1 = __ldg(src + (size_t)(k0 + 1) * 128);
        const float f2 = __ldg(src + (size_t)(k0 + 8) * 128);
        const float f3 = __ldg(src + (size_t)(k0 + 9) * 128);
        unsigned h0, l0, h1, l1;
        split_pair_h(f0, f1, h0, l0);
        split_pair_h(f2, f3, h1, l1);
        ulonglong2 v;
        v.x = (unsigned long long)h0 | ((unsigned long long)h1 << 32);
        v.y = (unsigned long long)l0 | ((unsigned long long)l1 << 32);
        BHL[(ks * 32 + ctg) * 32 + ln] = v;
    }

    const int tg   = wid & 7;      // t-group: rows tg*16 .. tg*16+15
    const int cg   = wid >> 3;     // 0: x-cols (e), 1: h-cols (j)
    const int row0 = tg * 16 + (lane >> 2);
    const int qk   = (lane & 3) * 2;

    // phase-1 role
    const int t_ph1 = tid & 127;
    const int slab  = (tid >> 7) << 4;

    // grid-point geometry for phase 1 (constant per thread except g0)
    // computed inline each tile.

    // ---- phase 1 for the first tile into buf 0 ----
    const int tile0 = rank;
    {
        const int g0 = tile0 * TP;
        if (slab < kSteps * 16) {
            const int g  = g0 + t_ph1;
            const int ix = g / 2304;
            const int rm = g - ix * 2304;
            const int iy = rm / 48;
            const int iz = rm - iy * 48;
            const float gx = orgb[0] + (float)ix * stpb[0];
            const float gy = orgb[1] + (float)iy * stpb[1];
            const float gz = orgb[2] + (float)iz * stpb[2];
            #pragma unroll
            for (int k = 0; k < 16; k += 2) {
                const int n0 = slab + k;
                float w0 = 0.f, w1 = 0.f;
                {
                    const float dx = gx - poss[n0 * 3 + 0];
                    const float dy = gy - poss[n0 * 3 + 1];
                    const float dz = gz - poss[n0 * 3 + 2];
                    if (n0 < bn) w0 = __fdividef(s, s2 + dx*dx + dy*dy + dz*dz);
                }
                {
                    const float dx = gx - poss[n0 * 3 + 3];
                    const float dy = gy - poss[n0 * 3 + 4];
                    const float dz = gz - poss[n0 * 3 + 5];
                    if (n0 + 1 < bn) w1 = __fdividef(s, s2 + dx*dx + dy*dy + dz*dz);
                }
                __half2 hw = __floats2half2_rn(w0, w1);
                wb[0][t_ph1 * WST + (n0 >> 1)] = *(unsigned*)&hw;
            }
        }
    }
    __syncthreads();

    int cur = 0;
    for (int tile = tile0; tile < TILES_PER_B; tile += nblk, cur ^= 1) {
        const int g0 = tile * TP;

        // ===== load A fragments from wb[cur] =====
        unsigned aH[4][4];
        #pragma unroll
        for (int ks = 0; ks < 4; ks++) if (ks < kSteps) {
            const unsigned* w0 = wb[cur] + row0 * WST + ks * 8 + (lane & 3);
            const unsigned* w8 = wb[cur] + (row0 + 8) * WST + ks * 8 + (lane & 3);
            aH[ks][0] = w0[0];
            aH[ks][1] = w8[0];
            aH[ks][2] = w0[4];
            aH[ks][3] = w8[4];
        }

        // ===== phase 1 for next tile into wb[cur^1] (overlaps GEMM) =====
        const int ntile = tile + nblk;
        if (ntile < TILES_PER_B && slab < kSteps * 16) {
            const int g  = ntile * TP + t_ph1;
            const int ix = g / 2304;
            const int rm = g - ix * 2304;
            const int iy = rm / 48;
            const int iz = rm - iy * 48;
            const float gx = orgb[0] + (float)ix * stpb[0];
            const float gy = orgb[1] + (float)iy * stpb[1];
            const float gz = orgb[2] + (float)iz * stpb[2];
            #pragma unroll
            for (int k = 0; k < 16; k += 2) {
                const int n0 = slab + k;
                float w0 = 0.f, w1 = 0.f;
                {
                    const float dx = gx - poss[n0 * 3 + 0];
                    const float dy = gy - poss[n0 * 3 + 1];
                    const float dz = gz - poss[n0 * 3 + 2];
                    if (n0 < bn) w0 = __fdividef(s, s2 + dx*dx + dy*dy + dz*dz);
                }
                {
                    const float dx = gx - poss[n0 * 3 + 3];
                    const float dy = gy - poss[n0 * 3 + 4];
                    const float dz = gz - poss[n0 * 3 + 5];
                    if (n0 + 1 < bn) w1 = __fdividef(s, s2 + dx*dx + dy*dy + dz*dz);
                }
                __half2 hw = __floats2half2_rn(w0, w1);
                wb[cur ^ 1][t_ph1 * WST + (n0 >> 1)] = *(unsigned*)&hw;
            }
        }

        // ===== GEMM: c[ct][4], 16 col-tiles of this warp's half =====
        float c[16][4];
        #pragma unroll
        for (int ct = 0; ct < 16; ct++)
            #pragma unroll
            for (int r = 0; r < 4; r++) c[ct][r] = 0.f;

        #pragma unroll
        for (int ks = 0; ks < 4; ks++) if (ks < kSteps) {
            #pragma unroll
            for (int ct = 0; ct < 16; ct++) {
                const ulonglong2 bb = BHL[(ks * 32 + cg * 16 + ct) * 32 + lane];
                mma16816(c[ct], aH[ks], (unsigned)bb.x, (unsigned)(bb.x >> 32));
                mma16816(c[ct], aH[ks], (unsigned)bb.y, (unsigned)(bb.y >> 32));
            }
        }

        // ===== epilogue =====
        if (cg == 0) {
            const size_t base = ((size_t)b * GSZ + g0) * 128;
            #pragma unroll
            for (int ct = 0; ct < 16; ct++) {
                const int e0 = ct * 8 + qk;
                *(float2*)&cout[base + (size_t)row0 * 128 + e0] =
                    make_float2(c[ct][0], c[ct][1]);
                *(float2*)&cout[base + (size_t)(row0 + 8) * 128 + e0] =
                    make_float2(c[ct][2], c[ct][3]);
            }
        } else {
            float v0 = 0.f, v1 = 0.f;
            #pragma unroll
            for (int ct = 0; ct < 16; ct++) {
                const int j0 = ct * 8 + qk;
                const float b1a = b1s[j0], b1b = b1s[j0 + 1];
                const float w2a = W2s[j0], w2b = W2s[j0 + 1];
                v0 += fmaxf(c[ct][0] + b1a, 0.f) * w2a
                    + fmaxf(c[ct][1] + b1b, 0.f) * w2b;
                v1 += fmaxf(c[ct][2] + b1a, 0.f) * w2a
                    + fmaxf(c[ct][3] + b1b, 0.f) * w2b;
            }
            v0 += __shfl_xor_sync(0xffffffffu, v0, 1);
            v0 += __shfl_xor_sync(0xffffffffu, v0, 2);
            v1 += __shfl_xor_sync(0xffffffffu, v1, 1);
            v1 += __shfl_xor_sync(0xffffffffu, v1, 2);
            if ((lane & 3) == 0) {
                out[(size_t)b * GSZ + g0 + row0]     = v0 + b2v;
                out[(size_t)b * GSZ + g0 + row0 + 8] = v1 + b2v;
            }
        }
        __syncthreads();   // wb[cur^1] complete; wb[cur] free for reuse
    }
}

extern "C" void kernel_launch(void* const* d_in, const int* in_sizes, int n_in,
                              void* d_out, int out_size)
{
    const float* pos     = (const float*)d_in[0];
    const float* feat    = (const float*)d_in[1];
    const float* origin  = (const float*)d_in[2];
    const float* lattice = (const float*)d_in[3];
    const float* scale   = (const float*)d_in[4];
    const float* W1      = (const float*)d_in[5];
    const float* b1      = (const float*)d_in[6];
    const float* W2      = (const float*)d_in[7];
    const float* b2      = (const float*)d_in[8];
    const int*   bn      = (const int*)  d_in[9];

    float* out  = (float*)d_out;                 // [B,48,48,48]
    float* cout = out + (size_t)4 * GSZ;         // [B,48,48,48,128]

    prep_kernel<<<32, 256>>>(feat, W1);

    cudaFuncSetAttribute(dgnn7_kernel,
                         cudaFuncAttributeMaxDynamicSharedMemorySize, SMEM_BYTES);
    dgnn7_kernel<<<NBLK, THREADS, SMEM_BYTES>>>(
        pos, feat, origin, lattice, scale, b1, W2, b2, bn, out, cout);
}

// round 8
// speedup vs baseline: 9.4582x; 1.1501x over previous
#include <cuda_runtime.h>
#include <cuda_fp16.h>
#include <cstdint>

#define GSZ     (48*48*48)        // 110592
#define TP      64
#define THREADS 512
#define NBLK    296
#define TILES_PER_B (GSZ/TP)      // 1728
#define WST     36                // wbuf row stride (u32 / half2 units)

// smem float offsets
#define OFF_BHL 0                 // ulonglong2[4][32][32] = 16384 floats
#define OFF_WB0 16384             // 64*36 u32 = 2304
#define OFF_WB1 18688
#define OFF_RED 20992             // 2 parity x 2 halves x 64 rows = 256
#define OFF_B1  21248
#define OFF_W2  21376
#define OFF_POS 21504
#define OFF_ORG 21696
#define OFF_STP 21700
#define SMEM_BYTES (21760 * 4)    // 85 KB -> 2 blocks/SM = 170 KB

__device__ float FWg[4 * 64 * 128];

// ---- helpers ----
__device__ __forceinline__ void mma16816(float c[4], const unsigned a[4],
                                         unsigned b0, unsigned b1) {
    asm volatile(
        "mma.sync.aligned.m16n8k16.row.col.f32.f16.f16.f32 "
        "{%0,%1,%2,%3}, {%4,%5,%6,%7}, {%8,%9}, {%0,%1,%2,%3};"
        : "+f"(c[0]), "+f"(c[1]), "+f"(c[2]), "+f"(c[3])
        : "r"(a[0]), "r"(a[1]), "r"(a[2]), "r"(a[3]), "r"(b0), "r"(b1));
}
__device__ __forceinline__ void split_pair_h(float f0, float f1,
                                             unsigned &h, unsigned &l) {
    __half2 hh = __floats2half2_rn(f0, f1);
    h = *(unsigned*)&hh;
    float2 bk = __half22float2(hh);
    __half2 ll = __floats2half2_rn(f0 - bk.x, f1 - bk.y);
    l = *(unsigned*)&ll;
}

// ---------------- prep: FW[b][n][j] = sum_e F[b][n][e] * W1[e][j] ----------
__global__ void __launch_bounds__(256, 1)
prep_kernel(const float* __restrict__ feat, const float* __restrict__ W1)
{
    const int task = blockIdx.x * 256 + threadIdx.x;   // 8192
    const int j4   = (task & 31) * 4;
    const int bn_  = task >> 5;
    const float* frow = feat + (size_t)bn_ * 128;
    float4 acc = make_float4(0.f, 0.f, 0.f, 0.f);
    #pragma unroll 8
    for (int e = 0; e < 128; e++) {
        const float  fv = __ldg(frow + e);
        const float4 wv = __ldg((const float4*)(W1 + e * 128 + j4));
        acc.x += fv * wv.x; acc.y += fv * wv.y;
        acc.z += fv * wv.z; acc.w += fv * wv.w;
    }
    *(float4*)&FWg[(size_t)bn_ * 128 + j4] = acc;
}

// ---------------- main ------------------------------------------------------
__global__ void __launch_bounds__(THREADS, 2)
dgnn8_kernel(const float* __restrict__ pos,
             const float* __restrict__ feat,
             const float* __restrict__ origin,
             const float* __restrict__ lattice,
             const float* __restrict__ scale_p,
             const float* __restrict__ b1,
             const float* __restrict__ W2,
             const float* __restrict__ b2_p,
             const int*   __restrict__ bnodes,
             float* __restrict__ out,
             float* __restrict__ cout)
{
    extern __shared__ float sm[];
    ulonglong2* BHL = (ulonglong2*)(sm + OFF_BHL);   // [(ks*32+ctg)*32+lane] = {Bh,Bl}
    unsigned* wb[2] = { (unsigned*)(sm + OFF_WB0), (unsigned*)(sm + OFF_WB1) };
    float* red  = sm + OFF_RED;
    float* b1s  = sm + OFF_B1;
    float* W2s  = sm + OFF_W2;
    float* poss = sm + OFF_POS;
    float* orgb = sm + OFF_ORG;
    float* stpb = sm + OFF_STP;

    const int tid  = threadIdx.x;
    const int wid  = tid >> 5;
    const int lane = tid & 31;

    // ---- block -> batch allocation (weight ~ per-tile cost) ----
    int bn4[4], wgt[4], wsum = 0;
    #pragma unroll
    for (int i = 0; i < 4; i++) {
        bn4[i] = bnodes[i];
        wgt[i] = 2 * ((bn4[i] + 15) >> 4) + 2;
        wsum  += wgt[i];
    }
    int bnd[5]; bnd[0] = 0;
    { int cum = 0;
      #pragma unroll
      for (int i = 0; i < 4; i++) { cum += wgt[i];
          bnd[i + 1] = (2 * NBLK * cum + wsum) / (2 * wsum); } }
    int b = 0;
    while (b < 3 && (int)blockIdx.x >= bnd[b + 1]) b++;
    const int rank   = blockIdx.x - bnd[b];
    const int nblk   = bnd[b + 1] - bnd[b];
    const int bn     = bn4[b];
    const int kSteps = (bn + 15) >> 4;

    // ---- prologue: constants ----
    if (tid < 128) { b1s[tid] = b1[tid]; W2s[tid] = W2[tid]; }
    if (tid < 192) poss[tid] = pos[b * 192 + tid];
    if (tid < 3) {
        orgb[tid] = origin[b * 3 + tid];
        stpb[tid] = lattice[b * 9 + tid * 4] * (1.0f / 47.0f);
    }
    const float s   = scale_p[0];
    const float s2  = s * s;
    const float b2v = b2_p[0];

    // ---- B fragments (once): rows [F | FW], fp16 hi + residual lo.
    // Column permutation (within 16-col pair groups) so C frags form float4:
    // logical col = (ctg&~1)*8 + 4*(p>>1) + 2*(ctg&1) + (p&1), p = lane>>2.
    for (int task = tid; task < 4096; task += THREADS) {
        const int ln  = task & 31;
        const int ctg = (task >> 5) & 31;
        const int ks  = task >> 10;
        const int p   = ln >> 2;
        const int lcol = (ctg & ~1) * 8 + 4 * (p >> 1) + 2 * (ctg & 1) + (p & 1);
        const int k0  = ks * 16 + (ln & 3) * 2;
        const float* src = (lcol < 128)
            ? (feat + (size_t)b * 8192 + lcol)
            : (FWg + (size_t)b * 8192 + (lcol - 128));
        const float f0 = __ldg(src + (size_t)k0 * 128);
        const float f1 = __ldg(src + (size_t)(k0 + 1) * 128);
        const float f2 = __ldg(src + (size_t)(k0 + 8) * 128);
        const float f3 = __ldg(src + (size_t)(k0 + 9) * 128);
        unsigned h0, l0, h1, l1;
        split_pair_h(f0, f1, h0, l0);
        split_pair_h(f2, f3, h1, l1);
        ulonglong2 v;
        v.x = (unsigned long long)h0 | ((unsigned long long)h1 << 32);
        v.y = (unsigned long long)l0 | ((unsigned long long)l1 << 32);
        BHL[(ks * 32 + ctg) * 32 + ln] = v;
    }

    const int tg   = wid >> 2;        // 0..3: rows tg*16..+15
    const int cg   = wid & 3;         // 0,1: x cols; 2,3: h cols
    const int row0 = tg * 16 + (lane >> 2);
    const int q    = lane & 3;

    // phase-1 role: 64 rows x 8-atom slabs
    const int t_ph1 = tid & 63;
    const int slab  = (tid >> 6) << 3;

    // ---- phase 1 for first tile into buf 0 ----
    const int tile0 = rank;
    {
        const int g0 = tile0 * TP;
        if (slab < kSteps * 16) {
            const int g  = g0 + t_ph1;
            const int ix = g / 2304;
            const int rm = g - ix * 2304;
            const int iy = rm / 48;
            const int iz = rm - iy * 48;
            const float gx = orgb[0] + (float)ix * stpb[0];
            const float gy = orgb[1] + (float)iy * stpb[1];
            const float gz = orgb[2] + (float)iz * stpb[2];
            unsigned pk[4];
            #pragma unroll
            for (int k = 0; k < 8; k += 2) {
                const int n0 = slab + k;
                float w0 = 0.f, w1 = 0.f;
                {
                    const float dx = gx - poss[n0 * 3 + 0];
                    const float dy = gy - poss[n0 * 3 + 1];
                    const float dz = gz - poss[n0 * 3 + 2];
                    if (n0 < bn) w0 = __fdividef(s, s2 + dx*dx + dy*dy + dz*dz);
                }
                {
                    const float dx = gx - poss[n0 * 3 + 3];
                    const float dy = gy - poss[n0 * 3 + 4];
                    const float dz = gz - poss[n0 * 3 + 5];
                    if (n0 + 1 < bn) w1 = __fdividef(s, s2 + dx*dx + dy*dy + dz*dz);
                }
                __half2 hw = __floats2half2_rn(w0, w1);
                pk[k >> 1] = *(unsigned*)&hw;
            }
            *(uint4*)&wb[0][t_ph1 * WST + (slab >> 1)] =
                make_uint4(pk[0], pk[1], pk[2], pk[3]);
        }
    }
    __syncthreads();

    int cur = 0;
    for (int tile = tile0; tile < TILES_PER_B; tile += nblk, cur ^= 1) {
        const int g0 = tile * TP;

        // ===== phase 1 for next tile into wb[cur^1] (overlaps GEMM) =====
        const int ntile = tile + nblk;
        if (ntile < TILES_PER_B && slab < kSteps * 16) {
            const int g  = ntile * TP + t_ph1;
            const int ix = g / 2304;
            const int rm = g - ix * 2304;
            const int iy = rm / 48;
            const int iz = rm - iy * 48;
            const float gx = orgb[0] + (float)ix * stpb[0];
            const float gy = orgb[1] + (float)iy * stpb[1];
            const float gz = orgb[2] + (float)iz * stpb[2];
            unsigned pk[4];
            #pragma unroll
            for (int k = 0; k < 8; k += 2) {
                const int n0 = slab + k;
                float w0 = 0.f, w1 = 0.f;
                {
                    const float dx = gx - poss[n0 * 3 + 0];
                    const float dy = gy - poss[n0 * 3 + 1];
                    const float dz = gz - poss[n0 * 3 + 2];
                    if (n0 < bn) w0 = __fdividef(s, s2 + dx*dx + dy*dy + dz*dz);
                }
                {
                    const float dx = gx - poss[n0 * 3 + 3];
                    const float dy = gy - poss[n0 * 3 + 4];
                    const float dz = gz - poss[n0 * 3 + 5];
                    if (n0 + 1 < bn) w1 = __fdividef(s, s2 + dx*dx + dy*dy + dz*dz);
                }
                __half2 hw = __floats2half2_rn(w0, w1);
                pk[k >> 1] = *(unsigned*)&hw;
            }
            *(uint4*)&wb[cur ^ 1][t_ph1 * WST + (slab >> 1)] =
                make_uint4(pk[0], pk[1], pk[2], pk[3]);
        }

        // ===== GEMM: c[8][4] over this warp's 8 col-tiles =====
        float c[8][4];
        #pragma unroll
        for (int ct = 0; ct < 8; ct++)
            #pragma unroll
            for (int r = 0; r < 4; r++) c[ct][r] = 0.f;

        #pragma unroll
        for (int ks = 0; ks < 4; ks++) if (ks < kSteps) {
            unsigned aH[4];
            const unsigned* w0 = wb[cur] + row0 * WST + ks * 8 + q;
            const unsigned* w8 = wb[cur] + (row0 + 8) * WST + ks * 8 + q;
            aH[0] = w0[0]; aH[1] = w8[0]; aH[2] = w0[4]; aH[3] = w8[4];
            #pragma unroll
            for (int ct = 0; ct < 8; ct++) {
                const ulonglong2 bb = BHL[(ks * 32 + cg * 8 + ct) * 32 + lane];
                mma16816(c[ct], aH, (unsigned)bb.x, (unsigned)(bb.x >> 32));
                mma16816(c[ct], aH, (unsigned)bb.y, (unsigned)(bb.y >> 32));
            }
        }

        // ===== epilogue =====
        if (cg < 2) {
            // x -> cout, float4 per ct-pair thanks to column permutation
            const size_t base = ((size_t)b * GSZ + g0) * 128;
            #pragma unroll
            for (int i = 0; i < 4; i++) {
                const int e0 = cg * 64 + 16 * i + 4 * q;
                float4 v0 = make_float4(c[2*i][0], c[2*i][1], c[2*i+1][0], c[2*i+1][1]);
                float4 v1 = make_float4(c[2*i][2], c[2*i][3], c[2*i+1][2], c[2*i+1][3]);
                *(float4*)&cout[base + (size_t)row0 * 128 + e0]       = v0;
                *(float4*)&cout[base + (size_t)(row0 + 8) * 128 + e0] = v1;
            }
        } else {
            // h: relu(h+b1)*W2, partial over this warp's 64 j
            float v0 = 0.f, v1 = 0.f;
            #pragma unroll
            for (int ct = 0; ct < 8; ct++) {
                const int j0 = cg * 64 + (ct & ~1) * 8 + 4 * q + 2 * (ct & 1) - 128;
                const float2 bb = *(const float2*)&b1s[j0];
                const float2 ww = *(const float2*)&W2s[j0];
                v0 += fmaxf(c[ct][0] + bb.x, 0.f) * ww.x
                    + fmaxf(c[ct][1] + bb.y, 0.f) * ww.y;
                v1 += fmaxf(c[ct][2] + bb.x, 0.f) * ww.x
                    + fmaxf(c[ct][3] + bb.y, 0.f) * ww.y;
            }
            v0 += __shfl_xor_sync(0xffffffffu, v0, 1);
            v0 += __shfl_xor_sync(0xffffffffu, v0, 2);
            v1 += __shfl_xor_sync(0xffffffffu, v1, 1);
            v1 += __shfl_xor_sync(0xffffffffu, v1, 2);
            if (q == 0) {
                float* rd = red + cur * 128 + (cg - 2) * 64;
                rd[row0]     = v0;
                rd[row0 + 8] = v1;
            }
        }
        __syncthreads();   // wb swap + red[cur] complete

        // out for this tile (reads red[cur]; safe vs next tile via parity)
        if (tid < 64)
            out[(size_t)b * GSZ + g0 + tid] =
                red[cur * 128 + tid] + red[cur * 128 + 64 + tid] + b2v;
    }
}

extern "C" void kernel_launch(void* const* d_in, const int* in_sizes, int n_in,
                              void* d_out, int out_size)
{
    const float* pos     = (const float*)d_in[0];
    const float* feat    = (const float*)d_in[1];
    const float* origin  = (const float*)d_in[2];
    const float* lattice = (const float*)d_in[3];
    const float* scale   = (const float*)d_in[4];
    const float* W1      = (const float*)d_in[5];
    const float* b1      = (const float*)d_in[6];
    const float* W2      = (const float*)d_in[7];
    const float* b2      = (const float*)d_in[8];
    const int*   bn      = (const int*)  d_in[9];

    float* out  = (float*)d_out;                 // [B,48,48,48]
    float* cout = out + (size_t)4 * GSZ;         // [B,48,48,48,128]

    prep_kernel<<<32, 256>>>(feat, W1);

    cudaFuncSetAttribute(dgnn8_kernel,
                         cudaFuncAttributeMaxDynamicSharedMemorySize, SMEM_BYTES);
    dgnn8_kernel<<<NBLK, THREADS, SMEM_BYTES>>>(
        pos, feat, origin, lattice, scale, b1, W2, b2, bn, out, cout);
}

// round 9
// speedup vs baseline: 12.8916x; 1.3630x over previous
#include <cuda_runtime.h>
#include <cuda_fp16.h>
#include <cstdint>

#define GSZ     (48*48*48)        // 110592
#define TP      64
#define THREADS 512
#define NBLK    296
#define TILES_PER_B (GSZ/TP)      // 1728
#define WST     36                // wbuf row stride (u32 / half2 units)

// smem float offsets
#define OFF_BH2 0                 // ulonglong2[4][16][32] = 8192 floats
#define OFF_WB0 8192              // 64*36 u32 = 2304
#define OFF_WB1 10496
#define OFF_RED 12800             // 2 parity x 4 cgh x 64 rows = 512
#define OFF_B1  13312
#define OFF_W2  13440
#define OFF_POS 13568
#define OFF_ORG 13760
#define OFF_STP 13764
#define SMEM_BYTES (13824 * 4)    // 55296 B -> 2 blocks/SM

__device__ float FWg[4 * 64 * 128];

// ---- helpers ----
__device__ __forceinline__ unsigned smem_u32(const void* p) {
    unsigned a;
    asm("{ .reg .u64 t; cvta.to.shared.u64 t, %1; cvt.u32.u64 %0, t; }" : "=r"(a) : "l"(p));
    return a;
}
__device__ __forceinline__ void mma16816(float c[4], const unsigned a[4],
                                         unsigned b0, unsigned b1) {
    asm volatile(
        "mma.sync.aligned.m16n8k16.row.col.f32.f16.f16.f32 "
        "{%0,%1,%2,%3}, {%4,%5,%6,%7}, {%8,%9}, {%0,%1,%2,%3};"
        : "+f"(c[0]), "+f"(c[1]), "+f"(c[2]), "+f"(c[3])
        : "r"(a[0]), "r"(a[1]), "r"(a[2]), "r"(a[3]), "r"(b0), "r"(b1));
}
__device__ __forceinline__ void ldmA(unsigned a[4], unsigned addr) {
    asm volatile("ldmatrix.sync.aligned.m8n8.x4.shared.b16 {%0,%1,%2,%3}, [%4];"
        : "=r"(a[0]), "=r"(a[1]), "=r"(a[2]), "=r"(a[3]) : "r"(addr));
}

// ---------------- prep: FW[b][n][j] = sum_e F[b][n][e] * W1[e][j] ----------
__global__ void __launch_bounds__(128, 8)
prep_kernel(const float* __restrict__ feat, const float* __restrict__ W1)
{
    __shared__ float frow[128];
    const int row = blockIdx.x;            // b*64+n, 0..255
    const int j   = threadIdx.x;
    frow[j] = feat[row * 128 + j];
    __syncthreads();
    float a0 = 0.f, a1 = 0.f, a2 = 0.f, a3 = 0.f;
    #pragma unroll 8
    for (int e = 0; e < 128; e += 4) {
        a0 += frow[e]     * __ldg(W1 + (e)     * 128 + j);
        a1 += frow[e + 1] * __ldg(W1 + (e + 1) * 128 + j);
        a2 += frow[e + 2] * __ldg(W1 + (e + 2) * 128 + j);
        a3 += frow[e + 3] * __ldg(W1 + (e + 3) * 128 + j);
    }
    FWg[row * 128 + j] = (a0 + a1) + (a2 + a3);
}

// ---------------- main ------------------------------------------------------
__global__ void __launch_bounds__(THREADS, 2)
dgnn9_kernel(const float* __restrict__ pos,
             const float* __restrict__ feat,
             const float* __restrict__ origin,
             const float* __restrict__ lattice,
             const float* __restrict__ scale_p,
             const float* __restrict__ b1,
             const float* __restrict__ W2,
             const float* __restrict__ b2_p,
             const int*   __restrict__ bnodes,
             float* __restrict__ out,
             float* __restrict__ cout)
{
    extern __shared__ float sm[];
    ulonglong2* BH2 = (ulonglong2*)(sm + OFF_BH2);   // [(ks*16+pair)*32+lane]
    unsigned* wb[2] = { (unsigned*)(sm + OFF_WB0), (unsigned*)(sm + OFF_WB1) };
    float* red  = sm + OFF_RED;
    float* b1s  = sm + OFF_B1;
    float* W2s  = sm + OFF_W2;
    float* poss = sm + OFF_POS;
    float* orgb = sm + OFF_ORG;
    float* stpb = sm + OFF_STP;

    const int tid  = threadIdx.x;
    const int wid  = tid >> 5;
    const int lane = tid & 31;
    const unsigned smb = smem_u32(sm);
    const unsigned wbu[2] = { smb + OFF_WB0 * 4, smb + OFF_WB1 * 4 };

    // ---- block -> batch allocation ----
    int bn4[4], wgt[4], wsum = 0;
    #pragma unroll
    for (int i = 0; i < 4; i++) {
        bn4[i] = bnodes[i];
        wgt[i] = ((bn4[i] + 15) >> 4) + 2;
        wsum  += wgt[i];
    }
    int bnd[5]; bnd[0] = 0;
    { int cum = 0;
      #pragma unroll
      for (int i = 0; i < 4; i++) { cum += wgt[i];
          bnd[i + 1] = (2 * NBLK * cum + wsum) / (2 * wsum); } }
    int b = 0;
    while (b < 3 && (int)blockIdx.x >= bnd[b + 1]) b++;
    const int rank   = blockIdx.x - bnd[b];
    const int nblk   = bnd[b + 1] - bnd[b];
    const int bn     = bn4[b];
    const int kSteps = (bn + 15) >> 4;

    // ---- prologue ----
    if (tid < 128) { b1s[tid] = b1[tid]; W2s[tid] = W2[tid]; }
    if (tid < 192) poss[tid] = pos[b * 192 + tid];
    if (tid < 3) {
        orgb[tid] = origin[b * 3 + tid];
        stpb[tid] = lattice[b * 9 + tid * 4] * (1.0f / 47.0f);
    }
    const float s   = scale_p[0];
    const float s2  = s * s;
    const float b2v = b2_p[0];

    // ---- B fragments (fp16, col-permuted, 2 ct packed per ulonglong2) ----
    // lcol(ctg, p) = (ctg&~1)*8 + 4*(p>>1) + 2*(ctg&1) + (p&1);  ctg = 2*pair(+1)
    for (int task = tid; task < 2048; task += THREADS) {
        const int ln   = task & 31;
        const int pair = (task >> 5) & 15;
        const int ks   = task >> 9;
        const int p    = ln >> 2;
        const int lcol0 = pair * 16 + 4 * (p >> 1) + (p & 1);
        const int k0   = ks * 16 + (ln & 3) * 2;
        ulonglong2 v;
        #pragma unroll
        for (int o = 0; o < 2; o++) {
            const int col = lcol0 + 2 * o;
            const float* src = (col < 128)
                ? (feat + (size_t)b * 8192 + col)
                : (FWg + (size_t)b * 8192 + (col - 128));
            __half2 h0 = __floats2half2_rn(__ldg(src + (size_t)k0 * 128),
                                           __ldg(src + (size_t)(k0 + 1) * 128));
            __half2 h1 = __floats2half2_rn(__ldg(src + (size_t)(k0 + 8) * 128),
                                           __ldg(src + (size_t)(k0 + 9) * 128));
            unsigned long long u = (unsigned long long)(*(unsigned*)&h0)
                                 | ((unsigned long long)(*(unsigned*)&h1) << 32);
            if (o == 0) v.x = u; else v.y = u;
        }
        BH2[(ks * 16 + pair) * 32 + ln] = v;
    }

    const int tg  = wid >> 3;         // 0..1: rows tg*32..+31
    const int cg  = wid & 7;          // 0..3: x cols; 4..7: h cols
    const int q   = lane & 3;
    const int rr  = lane >> 2;        // 0..7

    // phase-1 role
    const int t_ph1 = tid & 63;
    const int slab  = (tid >> 6) << 3;

    // ---- phase 1 for first tile into buf 0 ----
    const int tile0 = rank;
    {
        const int g0 = tile0 * TP;
        if (slab < kSteps * 16) {
            const int g  = g0 + t_ph1;
            const int ix = g / 2304;
            const int rm = g - ix * 2304;
            const int iy = rm / 48;
            const int iz = rm - iy * 48;
            const float gx = orgb[0] + (float)ix * stpb[0];
            const float gy = orgb[1] + (float)iy * stpb[1];
            const float gz = orgb[2] + (float)iz * stpb[2];
            unsigned pk[4];
            #pragma unroll
            for (int k = 0; k < 8; k += 2) {
                const int n0 = slab + k;
                float w0 = 0.f, w1 = 0.f;
                {
                    const float dx = gx - poss[n0 * 3 + 0];
                    const float dy = gy - poss[n0 * 3 + 1];
                    const float dz = gz - poss[n0 * 3 + 2];
                    if (n0 < bn) w0 = __fdividef(s, s2 + dx*dx + dy*dy + dz*dz);
                }
                {
                    const float dx = gx - poss[n0 * 3 + 3];
                    const float dy = gy - poss[n0 * 3 + 4];
                    const float dz = gz - poss[n0 * 3 + 5];
                    if (n0 + 1 < bn) w1 = __fdividef(s, s2 + dx*dx + dy*dy + dz*dz);
                }
                __half2 hw = __floats2half2_rn(w0, w1);
                pk[k >> 1] = *(unsigned*)&hw;
            }
            *(uint4*)&wb[0][t_ph1 * WST + (slab >> 1)] =
                make_uint4(pk[0], pk[1], pk[2], pk[3]);
        }
    }
    __syncthreads();

    int cur = 0;
    for (int tile = tile0; tile < TILES_PER_B; tile += nblk, cur ^= 1) {
        const int g0 = tile * TP;

        // ===== phase 1 for next tile into wb[cur^1] =====
        const int ntile = tile + nblk;
        if (ntile < TILES_PER_B && slab < kSteps * 16) {
            const int g  = ntile * TP + t_ph1;
            const int ix = g / 2304;
            const int rm = g - ix * 2304;
            const int iy = rm / 48;
            const int iz = rm - iy * 48;
            const float gx = orgb[0] + (float)ix * stpb[0];
            const float gy = orgb[1] + (float)iy * stpb[1];
            const float gz = orgb[2] + (float)iz * stpb[2];
            unsigned pk[4];
            #pragma unroll
            for (int k = 0; k < 8; k += 2) {
                const int n0 = slab + k;
                float w0 = 0.f, w1 = 0.f;
                {
                    const float dx = gx - poss[n0 * 3 + 0];
                    const float dy = gy - poss[n0 * 3 + 1];
                    const float dz = gz - poss[n0 * 3 + 2];
                    if (n0 < bn) w0 = __fdividef(s, s2 + dx*dx + dy*dy + dz*dz);
                }
                {
                    const float dx = gx - poss[n0 * 3 + 3];
                    const float dy = gy - poss[n0 * 3 + 4];
                    const float dz = gz - poss[n0 * 3 + 5];
                    if (n0 + 1 < bn) w1 = __fdividef(s, s2 + dx*dx + dy*dy + dz*dz);
                }
                __half2 hw = __floats2half2_rn(w0, w1);
                pk[k >> 1] = *(unsigned*)&hw;
            }
            *(uint4*)&wb[cur ^ 1][t_ph1 * WST + (slab >> 1)] =
                make_uint4(pk[0], pk[1], pk[2], pk[3]);
        }

        // ===== GEMM: c[2 mt][4 ct][4] =====
        float c[2][4][4];
        #pragma unroll
        for (int mt = 0; mt < 2; mt++)
            #pragma unroll
            for (int ct = 0; ct < 4; ct++)
                #pragma unroll
                for (int r = 0; r < 4; r++) c[mt][ct][r] = 0.f;

        #pragma unroll
        for (int ks = 0; ks < 4; ks++) if (ks < kSteps) {
            unsigned a0[4], a1[4];
            const unsigned abase = wbu[cur] +
                ((unsigned)((tg * 32 + (lane & 15)) * WST + ks * 8 + (lane >> 4) * 4)) * 4u;
            ldmA(a0, abase);
            ldmA(a1, abase + 16 * WST * 4);
            #pragma unroll
            for (int cp = 0; cp < 2; cp++) {
                const ulonglong2 bb = BH2[(ks * 16 + cg * 2 + cp) * 32 + lane];
                const unsigned bx0 = (unsigned)bb.x, bx1 = (unsigned)(bb.x >> 32);
                const unsigned by0 = (unsigned)bb.y, by1 = (unsigned)(bb.y >> 32);
                mma16816(c[0][2 * cp],     a0, bx0, bx1);
                mma16816(c[0][2 * cp + 1], a0, by0, by1);
                mma16816(c[1][2 * cp],     a1, bx0, bx1);
                mma16816(c[1][2 * cp + 1], a1, by0, by1);
            }
        }

        // ===== epilogue =====
        if (cg < 4) {
            const size_t base = ((size_t)b * GSZ + g0) * 128;
            #pragma unroll
            for (int mt = 0; mt < 2; mt++) {
                const int row0 = tg * 32 + mt * 16 + rr;
                #pragma unroll
                for (int i = 0; i < 2; i++) {
                    const int e0 = cg * 32 + 16 * i + 4 * q;
                    float4 v0 = make_float4(c[mt][2*i][0], c[mt][2*i][1],
                                            c[mt][2*i+1][0], c[mt][2*i+1][1]);
                    float4 v1 = make_float4(c[mt][2*i][2], c[mt][2*i][3],
                                            c[mt][2*i+1][2], c[mt][2*i+1][3]);
                    *(float4*)&cout[base + (size_t)row0 * 128 + e0]       = v0;
                    *(float4*)&cout[base + (size_t)(row0 + 8) * 128 + e0] = v1;
                }
            }
        } else {
            const int cgh = cg - 4;
            #pragma unroll
            for (int mt = 0; mt < 2; mt++) {
                float v0 = 0.f, v1 = 0.f;
                #pragma unroll
                for (int i = 0; i < 2; i++) {
                    const int jb = cgh * 32 + 16 * i + 4 * q;
                    const float4 bbv = *(const float4*)&b1s[jb];
                    const float4 wwv = *(const float4*)&W2s[jb];
                    v0 += fmaxf(c[mt][2*i][0]   + bbv.x, 0.f) * wwv.x
                        + fmaxf(c[mt][2*i][1]   + bbv.y, 0.f) * wwv.y
                        + fmaxf(c[mt][2*i+1][0] + bbv.z, 0.f) * wwv.z
                        + fmaxf(c[mt][2*i+1][1] + bbv.w, 0.f) * wwv.w;
                    v1 += fmaxf(c[mt][2*i][2]   + bbv.x, 0.f) * wwv.x
                        + fmaxf(c[mt][2*i][3]   + bbv.y, 0.f) * wwv.y
                        + fmaxf(c[mt][2*i+1][2] + bbv.z, 0.f) * wwv.z
                        + fmaxf(c[mt][2*i+1][3] + bbv.w, 0.f) * wwv.w;
                }
                v0 += __shfl_xor_sync(0xffffffffu, v0, 1);
                v0 += __shfl_xor_sync(0xffffffffu, v0, 2);
                v1 += __shfl_xor_sync(0xffffffffu, v1, 1);
                v1 += __shfl_xor_sync(0xffffffffu, v1, 2);
                if (q == 0) {
                    float* rd = red + cur * 256 + cgh * 64 + tg * 32 + mt * 16;
                    rd[rr]     = v0;
                    rd[rr + 8] = v1;
                }
            }
        }
        __syncthreads();

        if (tid < 64) {
            const float* rd = red + cur * 256;
            out[(size_t)b * GSZ + g0 + tid] =
                rd[tid] + rd[64 + tid] + rd[128 + tid] + rd[192 + tid] + b2v;
        }
    }
}

extern "C" void kernel_launch(void* const* d_in, const int* in_sizes, int n_in,
                              void* d_out, int out_size)
{
    const float* pos     = (const float*)d_in[0];
    const float* feat    = (const float*)d_in[1];
    const float* origin  = (const float*)d_in[2];
    const float* lattice = (const float*)d_in[3];
    const float* scale   = (const float*)d_in[4];
    const float* W1      = (const float*)d_in[5];
    const float* b1      = (const float*)d_in[6];
    const float* W2      = (const float*)d_in[7];
    const float* b2      = (const float*)d_in[8];
    const int*   bn      = (const int*)  d_in[9];

    float* out  = (float*)d_out;                 // [B,48,48,48]
    float* cout = out + (size_t)4 * GSZ;         // [B,48,48,48,128]

    prep_kernel<<<256, 128>>>(feat, W1);

    cudaFuncSetAttribute(dgnn9_kernel,
                         cudaFuncAttributeMaxDynamicSharedMemorySize, SMEM_BYTES);
    dgnn9_kernel<<<NBLK, THREADS, SMEM_BYTES>>>(
        pos, feat, origin, lattice, scale, b1, W2, b2, bn, out, cout);
}

// round 10
// speedup vs baseline: 14.6769x; 1.1385x over previous
#include <cuda_runtime.h>
#include <cuda_fp16.h>
#include <cstdint>

#define GSZ     (48*48*48)        // 110592
#define TP      64
#define THREADS 512
#define NBLK    296
#define TILES_PER_B (GSZ/TP)      // 1728
#define WST     36                // wbuf row stride (u32 / half2 units)

// smem float offsets
#define OFF_BH2 0                 // ulonglong2[4][16][32] = 8192 floats
#define OFF_WB0 8192              // 64*36 u32 = 2304
#define OFF_WB1 10496
#define OFF_RED 12800             // 2 parity x 4 cgh x 64 rows = 512
#define OFF_B1  13312
#define OFF_W2  13440
#define OFF_NEG 13568             // negx[64], negy[64], negz[64]
#define OFF_ORG 13760
#define OFF_STP 13764
#define SMEM_BYTES (13824 * 4)    // 55296 B -> 2 blocks/SM

typedef unsigned long long u64;

__device__ float FWg[4 * 64 * 128];

// ---- helpers ----
__device__ __forceinline__ unsigned smem_u32(const void* p) {
    unsigned a;
    asm("{ .reg .u64 t; cvta.to.shared.u64 t, %1; cvt.u32.u64 %0, t; }" : "=r"(a) : "l"(p));
    return a;
}
__device__ __forceinline__ u64 dup2(float f) {
    u64 r; asm("mov.b64 %0, {%1, %1};" : "=l"(r) : "f"(f)); return r;
}
__device__ __forceinline__ u64 add2(u64 a, u64 b) {
    u64 r; asm("add.rn.f32x2 %0, %1, %2;" : "=l"(r) : "l"(a), "l"(b)); return r;
}
__device__ __forceinline__ u64 fma2v(u64 a, u64 b, u64 c) {
    u64 r; asm("fma.rn.f32x2 %0, %1, %2, %3;" : "=l"(r) : "l"(a), "l"(b), "l"(c)); return r;
}
__device__ __forceinline__ float2 unpk(u64 v) {
    float2 r; asm("mov.b64 {%0, %1}, %2;" : "=f"(r.x), "=f"(r.y) : "l"(v)); return r;
}
__device__ __forceinline__ void mma16816(float c[4], const unsigned a[4],
                                         unsigned b0, unsigned b1) {
    asm volatile(
        "mma.sync.aligned.m16n8k16.row.col.f32.f16.f16.f32 "
        "{%0,%1,%2,%3}, {%4,%5,%6,%7}, {%8,%9}, {%0,%1,%2,%3};"
        : "+f"(c[0]), "+f"(c[1]), "+f"(c[2]), "+f"(c[3])
        : "r"(a[0]), "r"(a[1]), "r"(a[2]), "r"(a[3]), "r"(b0), "r"(b1));
}
__device__ __forceinline__ void ldmA(unsigned a[4], unsigned addr) {
    asm volatile("ldmatrix.sync.aligned.m8n8.x4.shared.b16 {%0,%1,%2,%3}, [%4];"
        : "=r"(a[0]), "=r"(a[1]), "=r"(a[2]), "=r"(a[3]) : "r"(addr));
}

// ---------------- prep: FW[b][n][j] = sum_e F[b][n][e] * W1[e][j] ----------
__global__ void __launch_bounds__(128, 8)
prep_kernel(const float* __restrict__ feat, const float* __restrict__ W1)
{
    __shared__ float frow[128];
    const int row = blockIdx.x;            // b*64+n, 0..255
    const int j   = threadIdx.x;
    frow[j] = feat[row * 128 + j];
    __syncthreads();
    float a0 = 0.f, a1 = 0.f, a2 = 0.f, a3 = 0.f;
    #pragma unroll 8
    for (int e = 0; e < 128; e += 4) {
        a0 += frow[e]     * __ldg(W1 + (e)     * 128 + j);
        a1 += frow[e + 1] * __ldg(W1 + (e + 1) * 128 + j);
        a2 += frow[e + 2] * __ldg(W1 + (e + 2) * 128 + j);
        a3 += frow[e + 3] * __ldg(W1 + (e + 3) * 128 + j);
    }
    FWg[row * 128 + j] = (a0 + a1) + (a2 + a3);
}

// ---------------- main ------------------------------------------------------
__global__ void __launch_bounds__(THREADS, 2)
dgnn10_kernel(const float* __restrict__ pos,
              const float* __restrict__ feat,
              const float* __restrict__ origin,
              const float* __restrict__ lattice,
              const float* __restrict__ scale_p,
              const float* __restrict__ b1,
              const float* __restrict__ W2,
              const float* __restrict__ b2_p,
              const int*   __restrict__ bnodes,
              float* __restrict__ out,
              float* __restrict__ cout)
{
    extern __shared__ float sm[];
    ulonglong2* BH2 = (ulonglong2*)(sm + OFF_BH2);   // [(ks*16+pair)*32+lane]
    unsigned* wb[2] = { (unsigned*)(sm + OFF_WB0), (unsigned*)(sm + OFF_WB1) };
    float* red  = sm + OFF_RED;
    float* b1s  = sm + OFF_B1;
    float* W2s  = sm + OFF_W2;
    float* negx = sm + OFF_NEG;
    float* negy = negx + 64;
    float* negz = negy + 64;
    float* orgb = sm + OFF_ORG;
    float* stpb = sm + OFF_STP;

    const int tid  = threadIdx.x;
    const int wid  = tid >> 5;
    const int lane = tid & 31;
    const unsigned smb = smem_u32(sm);
    const unsigned wbu[2] = { smb + OFF_WB0 * 4, smb + OFF_WB1 * 4 };

    // ---- block -> batch allocation ----
    int bn4[4], wgt[4], wsum = 0;
    #pragma unroll
    for (int i = 0; i < 4; i++) {
        bn4[i] = bnodes[i];
        wgt[i] = ((bn4[i] + 15) >> 4) + 2;
        wsum  += wgt[i];
    }
    int bnd[5]; bnd[0] = 0;
    { int cum = 0;
      #pragma unroll
      for (int i = 0; i < 4; i++) { cum += wgt[i];
          bnd[i + 1] = (2 * NBLK * cum + wsum) / (2 * wsum); } }
    int b = 0;
    while (b < 3 && (int)blockIdx.x >= bnd[b + 1]) b++;
    const int rank   = blockIdx.x - bnd[b];
    const int nblk   = bnd[b + 1] - bnd[b];
    const int bn     = bn4[b];
    const int kSteps = (bn + 15) >> 4;

    // ---- prologue ----
    if (tid < 128) { b1s[tid] = b1[tid]; W2s[tid] = W2[tid]; }
    if (tid < 192) {
        // negated, mask-baked positions: [axis][n]
        const int n  = tid & 63;
        const int ax = tid >> 6;
        const float p = pos[b * 192 + n * 3 + ax];
        const float v = (n < bn) ? -p : (ax == 0 ? -1.0e19f : 0.0f);
        sm[OFF_NEG + ax * 64 + n] = v;
    }
    if (tid < 3) {
        orgb[tid] = origin[b * 3 + tid];
        stpb[tid] = lattice[b * 9 + tid * 4] * (1.0f / 47.0f);
    }
    const float s   = scale_p[0];
    const float b2v = b2_p[0];
    const u64 s2d   = dup2(s * s);

    // ---- B fragments (fp16, col-permuted, 2 ct packed per ulonglong2) ----
    for (int task = tid; task < 2048; task += THREADS) {
        const int ln   = task & 31;
        const int pair = (task >> 5) & 15;
        const int ks   = task >> 9;
        const int p    = ln >> 2;
        const int lcol0 = pair * 16 + 4 * (p >> 1) + (p & 1);
        const int k0   = ks * 16 + (ln & 3) * 2;
        ulonglong2 v;
        #pragma unroll
        for (int o = 0; o < 2; o++) {
            const int col = lcol0 + 2 * o;
            const float* src = (col < 128)
                ? (feat + (size_t)b * 8192 + col)
                : (FWg + (size_t)b * 8192 + (col - 128));
            __half2 h0 = __floats2half2_rn(__ldg(src + (size_t)k0 * 128),
                                           __ldg(src + (size_t)(k0 + 1) * 128));
            __half2 h1 = __floats2half2_rn(__ldg(src + (size_t)(k0 + 8) * 128),
                                           __ldg(src + (size_t)(k0 + 9) * 128));
            u64 u = (u64)(*(unsigned*)&h0) | ((u64)(*(unsigned*)&h1) << 32);
            if (o == 0) v.x = u; else v.y = u;
        }
        BH2[(ks * 16 + pair) * 32 + ln] = v;
    }

    const int tg  = wid >> 3;         // 0..1: rows tg*32..+31
    const int cg  = wid & 7;          // 0..3: x cols; 4..7: h cols
    const int q   = lane & 3;
    const int rr  = lane >> 2;        // 0..7

    // phase-1 role
    const int t_ph1 = tid & 63;
    const int slab  = (tid >> 6) << 3;
    const bool ph1_on = slab < kSteps * 16;

    // packed f32x2 weight generator
    auto phase1 = [&](int g0, unsigned* dst) {
        const int g  = g0 + t_ph1;
        const int ix = g / 2304;
        const int rm = g - ix * 2304;
        const int iy = rm / 48;
        const int iz = rm - iy * 48;
        const u64 gxd = dup2(orgb[0] + (float)ix * stpb[0]);
        const u64 gyd = dup2(orgb[1] + (float)iy * stpb[1]);
        const u64 gzd = dup2(orgb[2] + (float)iz * stpb[2]);
        unsigned pk[4];
        #pragma unroll
        for (int p = 0; p < 4; p++) {
            const int n0 = slab + 2 * p;
            const u64 dx = add2(gxd, *(const u64*)&negx[n0]);
            const u64 dy = add2(gyd, *(const u64*)&negy[n0]);
            const u64 dz = add2(gzd, *(const u64*)&negz[n0]);
            u64 d2 = fma2v(dx, dx, s2d);
            d2 = fma2v(dy, dy, d2);
            d2 = fma2v(dz, dz, d2);
            const float2 f = unpk(d2);
            const float w0 = __fdividef(s, f.x);   // masked atoms -> ~5e-39 -> fp16 0
            const float w1 = __fdividef(s, f.y);
            __half2 hw = __floats2half2_rn(w0, w1);
            pk[p] = *(unsigned*)&hw;
        }
        *(uint4*)&dst[t_ph1 * WST + (slab >> 1)] =
            make_uint4(pk[0], pk[1], pk[2], pk[3]);
    };

    // ---- phase 1 for first tile into buf 0 ----
    const int tile0 = rank;
    if (ph1_on) phase1(tile0 * TP, wb[0]);
    __syncthreads();

    int cur = 0;
    for (int tile = tile0; tile < TILES_PER_B; tile += nblk, cur ^= 1) {
        const int g0 = tile * TP;

        // ===== phase 1 for next tile into wb[cur^1] (overlaps GEMM) =====
        const int ntile = tile + nblk;
        if (ntile < TILES_PER_B && ph1_on) phase1(ntile * TP, wb[cur ^ 1]);

        // ===== GEMM: c[2 mt][4 ct][4] =====
        float c[2][4][4];
        #pragma unroll
        for (int mt = 0; mt < 2; mt++)
            #pragma unroll
            for (int ct = 0; ct < 4; ct++)
                #pragma unroll
                for (int r = 0; r < 4; r++) c[mt][ct][r] = 0.f;

        #pragma unroll
        for (int ks = 0; ks < 4; ks++) if (ks < kSteps) {
            unsigned a0[4], a1[4];
            const unsigned abase = wbu[cur] +
                ((unsigned)((tg * 32 + (lane & 15)) * WST + ks * 8 + (lane >> 4) * 4)) * 4u;
            ldmA(a0, abase);
            ldmA(a1, abase + 16 * WST * 4);
            #pragma unroll
            for (int cp = 0; cp < 2; cp++) {
                const ulonglong2 bb = BH2[(ks * 16 + cg * 2 + cp) * 32 + lane];
                const unsigned bx0 = (unsigned)bb.x, bx1 = (unsigned)(bb.x >> 32);
                const unsigned by0 = (unsigned)bb.y, by1 = (unsigned)(bb.y >> 32);
                mma16816(c[0][2 * cp],     a0, bx0, bx1);
                mma16816(c[0][2 * cp + 1], a0, by0, by1);
                mma16816(c[1][2 * cp],     a1, bx0, bx1);
                mma16816(c[1][2 * cp + 1], a1, by0, by1);
            }
        }

        // ===== epilogue =====
        if (cg < 4) {
            const size_t base = ((size_t)b * GSZ + g0) * 128;
            #pragma unroll
            for (int mt = 0; mt < 2; mt++) {
                const int row0 = tg * 32 + mt * 16 + rr;
                #pragma unroll
                for (int i = 0; i < 2; i++) {
                    const int e0 = cg * 32 + 16 * i + 4 * q;
                    float4 v0 = make_float4(c[mt][2*i][0], c[mt][2*i][1],
                                            c[mt][2*i+1][0], c[mt][2*i+1][1]);
                    float4 v1 = make_float4(c[mt][2*i][2], c[mt][2*i][3],
                                            c[mt][2*i+1][2], c[mt][2*i+1][3]);
                    __stcs((float4*)&cout[base + (size_t)row0 * 128 + e0], v0);
                    __stcs((float4*)&cout[base + (size_t)(row0 + 8) * 128 + e0], v1);
                }
            }
        } else {
            const int cgh = cg - 4;
            #pragma unroll
            for (int mt = 0; mt < 2; mt++) {
                float v0 = 0.f, v1 = 0.f;
                #pragma unroll
                for (int i = 0; i < 2; i++) {
                    const int jb = cgh * 32 + 16 * i + 4 * q;
                    const float4 bbv = *(const float4*)&b1s[jb];
                    const float4 wwv = *(const float4*)&W2s[jb];
                    v0 += fmaxf(c[mt][2*i][0]   + bbv.x, 0.f) * wwv.x
                        + fmaxf(c[mt][2*i][1]   + bbv.y, 0.f) * wwv.y
                        + fmaxf(c[mt][2*i+1][0] + bbv.z, 0.f) * wwv.z
                        + fmaxf(c[mt][2*i+1][1] + bbv.w, 0.f) * wwv.w;
                    v1 += fmaxf(c[mt][2*i][2]   + bbv.x, 0.f) * wwv.x
                        + fmaxf(c[mt][2*i][3]   + bbv.y, 0.f) * wwv.y
                        + fmaxf(c[mt][2*i+1][2] + bbv.z, 0.f) * wwv.z
                        + fmaxf(c[mt][2*i+1][3] + bbv.w, 0.f) * wwv.w;
                }
                v0 += __shfl_xor_sync(0xffffffffu, v0, 1);
                v0 += __shfl_xor_sync(0xffffffffu, v0, 2);
                v1 += __shfl_xor_sync(0xffffffffu, v1, 1);
                v1 += __shfl_xor_sync(0xffffffffu, v1, 2);
                if (q == 0) {
                    float* rd = red + cur * 256 + cgh * 64 + tg * 32 + mt * 16;
                    rd[rr]     = v0;
                    rd[rr + 8] = v1;
                }
            }
        }
        __syncthreads();

        if (tid < 64) {
            const float* rd = red + cur * 256;
            out[(size_t)b * GSZ + g0 + tid] =
                rd[tid] + rd[64 + tid] + rd[128 + tid] + rd[192 + tid] + b2v;
        }
    }
}

extern "C" void kernel_launch(void* const* d_in, const int* in_sizes, int n_in,
                              void* d_out, int out_size)
{
    const float* pos     = (const float*)d_in[0];
    const float* feat    = (const float*)d_in[1];
    const float* origin  = (const float*)d_in[2];
    const float* lattice = (const float*)d_in[3];
    const float* scale   = (const float*)d_in[4];
    const float* W1      = (const float*)d_in[5];
    const float* b1      = (const float*)d_in[6];
    const float* W2      = (const float*)d_in[7];
    const float* b2      = (const float*)d_in[8];
    const int*   bn      = (const int*)  d_in[9];

    float* out  = (float*)d_out;                 // [B,48,48,48]
    float* cout = out + (size_t)4 * GSZ;         // [B,48,48,48,128]

    prep_kernel<<<256, 128>>>(feat, W1);

    cudaFuncSetAttribute(dgnn10_kernel,
                         cudaFuncAttributeMaxDynamicSharedMemorySize, SMEM_BYTES);
    dgnn10_kernel<<<NBLK, THREADS, SMEM_BYTES>>>(
        pos, feat, origin, lattice, scale, b1, W2, b2, bn, out, cout);
}